// round 13
// baseline (speedup 1.0000x reference)
#include <cuda_runtime.h>
#include <cuda_fp16.h>
#include <stdint.h>
#include <math.h>

#define NN 2000
#define EE 16000
#define BB 16
#define LL 256
#define HH 2000
#define FIN 100
#define GG 200

// ---------------- scratch (device globals; no cudaMalloc allowed) ----------------
__device__ float g_h[(size_t)NN * HH];
__device__ float g_tg[(size_t)NN * 10000];      // combined [etype(4000) | gh(6000)]
__device__ float g_gi[(size_t)NN * 3 * HH];
__device__ int   g_off[NN + 1];
__device__ int   g_cnt[NN];
__device__ int   g_csr[EE];
__device__ int   g_boff[BB + 1];
__device__ float g_gt[(size_t)LL * BB * 1200];
__device__ float g_WT[3 * 2 * 200 * 600];
__device__ float g_f1[BB * 1000];
__device__ float g_f2[BB * 500];
__device__ float g_bc[10000];

// fp16 operand buffers: A-side hi+lo, B-side (weights) hi only
__device__ __half g_hh[(size_t)2000 * 2048], g_hl[(size_t)2000 * 2048];
__device__ __half g_ah[(size_t)2000 * 2048], g_al[(size_t)2000 * 2048];
__device__ __half g_Wch[(size_t)10000 * 2048];
__device__ __half g_Wihh[(size_t)6000 * 2048];
__device__ __half g_gWh[(size_t)3600 * 448];
__device__ __half g_l1h[(size_t)1000 * 3200];
__device__ __half g_l11h[(size_t)500 * 1024];
__device__ __half g_xh[(size_t)4096 * 448], g_xl[(size_t)4096 * 448];
__device__ __half g_x2h[(size_t)4096 * 448], g_x2l[(size_t)4096 * 448];
__device__ __half g_ch[(size_t)16 * 3200], g_cl[(size_t)16 * 3200];
__device__ __half g_f1h[(size_t)16 * 1024], g_f1l[(size_t)16 * 1024];

// ---------------- small helpers ----------------
__device__ __forceinline__ float sigm(float x) { return 1.f / (1.f + expf(-x)); }
__device__ __forceinline__ float4 f4add(float4 a, float4 b) {
    return make_float4(a.x + b.x, a.y + b.y, a.z + b.z, a.w + b.w);
}
__device__ __forceinline__ void f4fma(float4& a, float4 w, float s) {
    a.x += w.x * s; a.y += w.y * s; a.z += w.z * s; a.w += w.w * s;
}
__device__ __forceinline__ void splitw(float v, __half& h, __half& l) {
    h = __float2half_rn(v);
    l = __float2half_rn(v - __half2float(h));
}
__device__ __forceinline__ uint32_t s2u(const void* p) {
    uint32_t a;
    asm("{ .reg .u64 t; cvta.to.shared.u64 t, %1; cvt.u32.u64 %0, t; }" : "=r"(a) : "l"(p));
    return a;
}
__device__ __forceinline__ void cpa16(uint32_t dst, const void* src, uint32_t sz) {
    asm volatile("cp.async.ca.shared.global [%0], [%1], 16, %2;" :: "r"(dst), "l"(src), "r"(sz));
}
__device__ __forceinline__ void ldm4(uint32_t* r, uint32_t addr) {
    asm volatile("ldmatrix.sync.aligned.m8n8.x4.shared.b16 {%0,%1,%2,%3}, [%4];"
                 : "=r"(r[0]), "=r"(r[1]), "=r"(r[2]), "=r"(r[3]) : "r"(addr));
}
__device__ __forceinline__ void hmma(float* c, const uint32_t* a, const uint32_t* b) {
    asm volatile("mma.sync.aligned.m16n8k16.row.col.f32.f16.f16.f32 "
                 "{%0,%1,%2,%3},{%4,%5,%6,%7},{%8,%9},{%0,%1,%2,%3};"
                 : "+f"(c[0]), "+f"(c[1]), "+f"(c[2]), "+f"(c[3])
                 : "r"(a[0]), "r"(a[1]), "r"(a[2]), "r"(a[3]), "r"(b[0]), "r"(b[1]));
}

// ============ fp16 2-term split GEMM: C = act((Ah+Al) @ Bh^T + bias) ============
// CTA tile 128(M) x 64(N), 256 threads (8 warps, 4x2 grid of 32x32 warp tiles),
// K-chunk 64, RS=144, double-buffered cp.async. TWO CTAs co-resident per SM so
// one CTA's HMMA covers the other's chunk-boundary stalls.
#define RS 144
#define MATAB (128 * RS)            // 18432 B per A tile
#define MATBB (64 * RS)             // 9216 B B tile
#define BUFB (2 * MATAB + MATBB)    // 46080 B
#define SMEM_DYN (2 * BUFB)         // 92160 B

__global__ __launch_bounds__(256, 2) void hgemm(
    const __half* __restrict__ Ah, const __half* __restrict__ Al, int ldA,
    const __half* __restrict__ Bh, int ldB,
    const float* __restrict__ bias, float* __restrict__ C, int ldc,
    int M, int N, int K, int act)
{
    extern __shared__ char smem[];
    const uint32_t sb = s2u(smem);
    const int tid = threadIdx.x;
    const int warp = tid >> 5, lane = tid & 31;
    const int wm = warp & 3, wn = warp >> 2;        // 4x2 warp grid, 32x32 tiles
    const int br = blockIdx.y * 128, bc = blockIdx.x * 64;
    const int nk = K >> 6;

    float acc[2][4][4];
#pragma unroll
    for (int mt = 0; mt < 2; mt++)
#pragma unroll
        for (int nt = 0; nt < 4; nt++)
#pragma unroll
            for (int r = 0; r < 4; r++) acc[mt][nt][r] = 0.f;

    auto issue = [&](int c) {
        uint32_t tb = sb + (uint32_t)(c & 1) * BUFB;
        int k0 = c << 6;
#pragma unroll
        for (int i = 0; i < 10; i++) {
            int g = (i << 8) + tid;           // 0..2559
            if (g < 2048) {
                int which = g >> 10;          // 0:Ah 1:Al
                int row = (g >> 3) & 127;
                int kb = g & 7;
                uint32_t dst = tb + which * MATAB + row * RS + kb * 16;
                int gr = br + row;
                const __half* base = which ? Al : Ah;
                uint32_t sz = (gr < M) ? 16u : 0u;
                cpa16(dst, base + (size_t)(gr < M ? gr : 0) * ldA + k0 + kb * 8, sz);
            } else {
                int g2 = g - 2048;            // 0..511
                int row = g2 >> 3;            // 0..63
                int kb = g2 & 7;
                uint32_t dst = tb + 2 * MATAB + row * RS + kb * 16;
                int gn = bc + row;
                uint32_t sz = (gn < N) ? 16u : 0u;
                cpa16(dst, Bh + (size_t)(gn < N ? gn : 0) * ldB + k0 + kb * 8, sz);
            }
        }
        asm volatile("cp.async.commit_group;");
    };

    const int arow = wm * 32 + (lane & 15);
    const int ak = (lane >> 4);
    const int brow = wn * 32 + (lane & 7) + ((lane >> 4) << 3);
    const int bk = ((lane >> 3) & 1);

    auto compute = [&](int c) {
        uint32_t tb = sb + (uint32_t)(c & 1) * BUFB;
        uint32_t aAh = tb, aAl = tb + MATAB, aBh = tb + 2 * MATAB;
#pragma unroll
        for (int k16 = 0; k16 < 4; k16++) {
            uint32_t ah[2][4], al[2][4];
#pragma unroll
            for (int mt = 0; mt < 2; mt++) {
                uint32_t off = (uint32_t)(arow + mt * 16) * RS + (2 * k16 + ak) * 16;
                ldm4(ah[mt], aAh + off);
                ldm4(al[mt], aAl + off);
            }
            uint32_t bh[4][2];
#pragma unroll
            for (int np = 0; np < 2; np++) {
                uint32_t off = (uint32_t)(brow + np * 16) * RS + (2 * k16 + bk) * 16;
                uint32_t t4[4];
                ldm4(t4, aBh + off);
                bh[np * 2][0] = t4[0]; bh[np * 2][1] = t4[1];
                bh[np * 2 + 1][0] = t4[2]; bh[np * 2 + 1][1] = t4[3];
            }
#pragma unroll
            for (int mt = 0; mt < 2; mt++)
#pragma unroll
                for (int nt = 0; nt < 4; nt++) {
                    hmma(acc[mt][nt], ah[mt], bh[nt]);
                    hmma(acc[mt][nt], al[mt], bh[nt]);
                }
        }
    };

    issue(0);
    for (int c = 0; c < nk; c++) {
        if (c + 1 < nk) {
            issue(c + 1);
            asm volatile("cp.async.wait_group 1;" ::: "memory");
        } else {
            asm volatile("cp.async.wait_group 0;" ::: "memory");
        }
        __syncthreads();
        compute(c);
        __syncthreads();
    }

#pragma unroll
    for (int mt = 0; mt < 2; mt++) {
        int row0 = br + wm * 32 + mt * 16 + (lane >> 2);
#pragma unroll
        for (int nt = 0; nt < 4; nt++) {
            int col = bc + wn * 32 + nt * 8 + ((lane & 3) << 1);
            if (col < N) {
                float b0 = bias ? bias[col] : 0.f;
                float b1 = bias ? bias[col + 1] : 0.f;
#pragma unroll
                for (int hi = 0; hi < 2; hi++) {
                    int row = row0 + hi * 8;
                    if (row < M) {
                        float2 v;
                        v.x = acc[mt][nt][hi * 2] + b0;
                        v.y = acc[mt][nt][hi * 2 + 1] + b1;
                        if (act) { v.x = fmaxf(v.x, 0.f); v.y = fmaxf(v.y, 0.f); }
                        *reinterpret_cast<float2*>(C + (size_t)row * ldc + col) = v;
                    }
                }
            }
        }
    }
}

// ---------------- split / convert kernels ----------------
__global__ void k_split(const float* __restrict__ in, __half* __restrict__ oh,
                        __half* __restrict__ ol, int R, int K, int Kp) {
    int idx = blockIdx.x * blockDim.x + threadIdx.x;
    if (idx >= R * Kp) return;
    int r = idx / Kp, c = idx - r * Kp;
    float v = (c < K) ? in[(size_t)r * K + c] : 0.f;
    splitw(v, oh[idx], ol[idx]);
}
__global__ void k_tohalf(const float* __restrict__ in, __half* __restrict__ oh,
                         int R, int K, int Kp) {
    int idx = blockIdx.x * blockDim.x + threadIdx.x;
    if (idx >= R * Kp) return;
    int r = idx / Kp, c = idx - r * Kp;
    float v = (c < K) ? in[(size_t)r * K + c] : 0.f;
    oh[idx] = __float2half_rn(v);
}
__global__ void k_splitfeats(const float* __restrict__ feats, __half* __restrict__ oh,
                             __half* __restrict__ ol) {
    int idx = blockIdx.x * blockDim.x + threadIdx.x;
    if (idx >= 2000 * 2048) return;
    int r = idx >> 11, c = idx & 2047;
    float v = (c < FIN) ? feats[r * FIN + c] : 0.f;
    splitw(v, oh[idx], ol[idx]);
}
__global__ void k_splitWc(const float* __restrict__ Wg, const float* __restrict__ Whh,
                          const float* __restrict__ bg, const float* __restrict__ bhh,
                          __half* __restrict__ oh, float* __restrict__ bc) {
    int idx = blockIdx.x * blockDim.x + threadIdx.x;
    if (idx >= 10000 * 2048) return;
    int r = idx >> 11, c = idx & 2047;
    float v = 0.f;
    if (c < 2000) v = (r < 4000) ? Wg[(size_t)r * 2000 + c] : Whh[(size_t)(r - 4000) * 2000 + c];
    oh[idx] = __float2half_rn(v);
    if (idx < 10000) bc[idx] = (idx < 4000) ? bg[idx] : bhh[idx - 4000];
}

// ---------------- CSR build ----------------
__global__ void k_zero_int(int* p, int n) {
    int i = blockIdx.x * blockDim.x + threadIdx.x;
    if (i < n) p[i] = 0;
}
__global__ void k_count(const int* __restrict__ dst, int* cnt) {
    int i = blockIdx.x * blockDim.x + threadIdx.x;
    if (i < EE) atomicAdd(&cnt[dst[i]], 1);
}
__global__ void k_scan(const int* __restrict__ cnt, int* __restrict__ off) {
    int tid = threadIdx.x;
    int a = (2 * tid < NN) ? cnt[2 * tid] : 0;
    int b = (2 * tid + 1 < NN) ? cnt[2 * tid + 1] : 0;
    int ts = a + b;
    int lane = tid & 31, wid = tid >> 5;
    int v = ts;
#pragma unroll
    for (int d = 1; d < 32; d <<= 1) {
        int u = __shfl_up_sync(0xffffffffu, v, d);
        if (lane >= d) v += u;
    }
    __shared__ int ws[32];
    if (lane == 31) ws[wid] = v;
    __syncthreads();
    if (wid == 0) {
        int w = ws[lane];
#pragma unroll
        for (int d = 1; d < 32; d <<= 1) {
            int u = __shfl_up_sync(0xffffffffu, w, d);
            if (lane >= d) w += u;
        }
        ws[lane] = w;
    }
    __syncthreads();
    int incl = v + (wid > 0 ? ws[wid - 1] : 0);
    int excl = incl - ts;
    if (2 * tid <= NN) off[2 * tid] = excl;
    if (2 * tid + 1 <= NN) off[2 * tid + 1] = excl + a;
}
__global__ void k_fill(const int* __restrict__ src, const int* __restrict__ dst,
                       const int* __restrict__ et, const int* __restrict__ off,
                       int* cnt, int* __restrict__ csr) {
    int i = blockIdx.x * blockDim.x + threadIdx.x;
    if (i < EE) {
        int d = dst[i];
        int p = off[d] + atomicAdd(&cnt[d], 1);
        csr[p] = src[i] * 2 + et[i];
    }
}
__global__ void k_boff(const int* __restrict__ batch, int* boff) {
    int i = blockIdx.x * blockDim.x + threadIdx.x;
    if (i >= NN) return;
    int b = batch[i];
    if (i == 0) {
        for (int x = 0; x <= b; x++) boff[x] = 0;
    } else {
        int pb = batch[i - 1];
        if (pb != b) for (int x = pb + 1; x <= b; x++) boff[x] = i;
    }
    if (i == NN - 1) {
        for (int x = b + 1; x <= BB; x++) boff[x] = NN;
    }
}

// ---------------- GGNN pieces (fused splits) ----------------
__global__ void k_hinit(const float* __restrict__ feats, float* __restrict__ h) {
    int i = blockIdx.x * blockDim.x + threadIdx.x;
    if (i >= NN * HH) return;
    int r = i / HH, c = i % HH;
    h[i] = (c < FIN) ? feats[r * FIN + c] : 0.f;
}
__global__ void k_agg(const float* __restrict__ tg, const int* __restrict__ off,
                      const int* __restrict__ csr, __half* __restrict__ ah,
                      __half* __restrict__ al) {
    int d = blockIdx.x;
    int j = blockIdx.y * 256 + threadIdx.x;   // 0..2047
    size_t o = (size_t)d * 2048 + j;
    if (j >= 2000) { ah[o] = __half(0.f); al[o] = __half(0.f); return; }
    int s0 = off[d], s1 = off[d + 1];
    float acc = 0.f;
    for (int p = s0; p < s1; p++) {
        int v = csr[p];
        int sn = v >> 1, e = v & 1;
        acc += tg[(size_t)sn * 10000 + e * 2000 + j];
    }
    splitw(acc, ah[o], al[o]);
}
__global__ void k_cell(const float* __restrict__ gi, const float* __restrict__ tg,
                       float* __restrict__ h, __half* __restrict__ hh,
                       __half* __restrict__ hl) {
    int i = blockIdx.x * blockDim.x + threadIdx.x;
    if (i >= NN * HH) return;
    int r = i / HH, c = i % HH;
    size_t gI = (size_t)r * 6000 + c;
    size_t gH = (size_t)r * 10000 + 4000 + c;
    float rr = sigm(gi[gI] + tg[gH]);
    float zz = sigm(gi[gI + 2000] + tg[gH + 2000]);
    float nn = tanhf(gi[gI + 4000] + rr * tg[gH + 4000]);
    float hv = (1.f - zz) * nn + zz * h[i];
    h[i] = hv;
    size_t o = (size_t)r * 2048 + c;
    splitw(hv, hh[o], hl[o]);
}
__global__ void k_segmax(const float* __restrict__ h, const int* __restrict__ boff,
                         __half* __restrict__ ch, __half* __restrict__ cl) {
    int b = blockIdx.y;
    int j = blockIdx.x * 256 + threadIdx.x;
    if (j >= HH) return;
    int s = boff[b], e = boff[b + 1];
    float m = -INFINITY;
    for (int i = s; i < e; i++) m = fmaxf(m, h[(size_t)i * HH + j]);
    splitw(m, ch[b * 3200 + j], cl[b * 3200 + j]);
}

// ---------------- token branch ----------------
__global__ void k_embed(const float* __restrict__ ew, const int* __restrict__ tokens,
                        __half* __restrict__ xh, __half* __restrict__ xl) {
    int tb = blockIdx.x;
    int t = tb / BB, b = tb % BB;
    int tok = tokens[b * LL + t];
    size_t ro = (size_t)tb * 448;
    for (int j = threadIdx.x; j < 448; j += blockDim.x) {
        float v = (j < FIN) ? ew[(size_t)tok * FIN + j] : 0.f;
        splitw(v, xh[ro + j], xl[ro + j]);
    }
}
__global__ void k_zpad(__half* __restrict__ xh, __half* __restrict__ xl) {
    int idx = blockIdx.x * blockDim.x + threadIdx.x;
    if (idx >= 4096 * 48) return;
    int r = idx / 48, c = 400 + idx % 48;
    xh[(size_t)r * 448 + c] = __half(0.f);
    xl[(size_t)r * 448 + c] = __half(0.f);
}
__global__ void k_transpose_whh(const float* __restrict__ W, float* __restrict__ WT) {
    int i = blockIdx.x * blockDim.x + threadIdx.x;
    if (i >= 6 * 600 * 200) return;
    int ld = i / (600 * 200);
    int rem = i % (600 * 200);
    int j = rem / 200, k = rem % 200;
    WT[ld * 120000 + k * 600 + j] = W[i];
}

__global__ __launch_bounds__(256) void k_gruscan(
    const float* __restrict__ giAll,
    const float* __restrict__ WTl,
    const float* __restrict__ bhhl,
    __half* __restrict__ yh, __half* __restrict__ yl,   // [L*B][448]
    __half* __restrict__ ch, __half* __restrict__ cl,
    int layer)
{
    int cid = blockIdx.x;
    int dir = cid & 1;
    int bp = cid >> 1;
    const float* W = WTl + dir * 120000;
    const float4* bh4 = reinterpret_cast<const float4*>(bhhl + dir * 600);

    __shared__ float sh_h[2][GG];
    __shared__ float sh_gi[2][600];
    __shared__ float4 red[4][50][6];

    int tid = threadIdx.x;
    int jg = tid & 63;
    int ks = tid >> 6;

    for (int i = tid; i < 2 * GG; i += 256) (&sh_h[0][0])[i] = 0.f;
    __syncthreads();

    for (int s = 0; s < LL; s++) {
        int t = dir ? (LL - 1 - s) : s;
        const float* gi0 = giAll + ((size_t)(t * BB + 2 * bp)) * 1200 + dir * 600;
        for (int i = tid; i < 600; i += 256) {
            sh_gi[0][i] = gi0[i];
            sh_gi[1][i] = gi0[1200 + i];
        }
        __syncthreads();

        if (jg < 50) {
            float4 a[6];
#pragma unroll
            for (int q = 0; q < 6; q++) a[q] = make_float4(0.f, 0.f, 0.f, 0.f);
            int kb = ks * 50;
            const float* Wp = W + (size_t)kb * 600;
            for (int k = 0; k < 50; k++) {
                float h0 = sh_h[0][kb + k];
                float h1 = sh_h[1][kb + k];
                const float4* w4 = reinterpret_cast<const float4*>(Wp + k * 600);
                float4 wr = w4[jg];
                float4 wz = w4[50 + jg];
                float4 wn = w4[100 + jg];
                f4fma(a[0], wr, h0); f4fma(a[1], wz, h0); f4fma(a[2], wn, h0);
                f4fma(a[3], wr, h1); f4fma(a[4], wz, h1); f4fma(a[5], wn, h1);
            }
#pragma unroll
            for (int q = 0; q < 6; q++) red[ks][jg][q] = a[q];
        }
        __syncthreads();

        if (tid < 100) {
            int b = tid / 50, j2 = tid % 50;
            float4 gr = f4add(f4add(red[0][j2][b * 3 + 0], red[1][j2][b * 3 + 0]),
                              f4add(red[2][j2][b * 3 + 0], red[3][j2][b * 3 + 0]));
            float4 gz = f4add(f4add(red[0][j2][b * 3 + 1], red[1][j2][b * 3 + 1]),
                              f4add(red[2][j2][b * 3 + 1], red[3][j2][b * 3 + 1]));
            float4 gn = f4add(f4add(red[0][j2][b * 3 + 2], red[1][j2][b * 3 + 2]),
                              f4add(red[2][j2][b * 3 + 2], red[3][j2][b * 3 + 2]));
            gr = f4add(gr, bh4[j2]);
            gz = f4add(gz, bh4[50 + j2]);
            gn = f4add(gn, bh4[100 + j2]);
            float grf[4] = {gr.x, gr.y, gr.z, gr.w};
            float gzf[4] = {gz.x, gz.y, gz.z, gz.w};
            float gnf[4] = {gn.x, gn.y, gn.z, gn.w};
            float hnew[4];
#pragma unroll
            for (int c = 0; c < 4; c++) {
                int j = j2 * 4 + c;
                float rr = sigm(sh_gi[b][j] + grf[c]);
                float zz = sigm(sh_gi[b][200 + j] + gzf[c]);
                float nn = tanhf(sh_gi[b][400 + j] + rr * gnf[c]);
                hnew[c] = (1.f - zz) * nn + zz * sh_h[b][j];
            }
            int gb = 2 * bp + b;
            size_t yo = ((size_t)(t * BB + gb)) * 448 + dir * 200 + j2 * 4;
#pragma unroll
            for (int c = 0; c < 4; c++) splitw(hnew[c], yh[yo + c], yl[yo + c]);
            if (s == LL - 1) {
                size_t co = (size_t)gb * 3200 + 2000 + (2 * layer + dir) * 200 + j2 * 4;
#pragma unroll
                for (int c = 0; c < 4; c++) splitw(hnew[c], ch[co + c], cl[co + c]);
            }
#pragma unroll
            for (int c = 0; c < 4; c++) sh_h[b][j2 * 4 + c] = hnew[c];
        }
        __syncthreads();
    }
}

// ---------------- final tiny head layer (N=2) ----------------
__global__ void k_head2(const float* __restrict__ f2, const float* __restrict__ W,
                        const float* __restrict__ b, float* __restrict__ out) {
    int t = threadIdx.x;
    if (t >= 32) return;
    int bb = t >> 1, n = t & 1;
    float acc = 0.f;
    for (int k = 0; k < 500; k++) acc += f2[bb * 500 + k] * W[n * 500 + k];
    out[bb * 2 + n] = fmaxf(acc + b[n], 0.f);
}

// ---------------- host side ----------------
#define SYMP(p, s) do { void* _q = nullptr; cudaGetSymbolAddress(&_q, s); p = (decltype(p))_q; } while (0)

static void tcg(cudaStream_t st, const __half* Ah, const __half* Al, int ldA,
                const __half* Bh, int ldB,
                const float* bias, float* C, int ldc, int M, int N, int K, int act) {
    dim3 g((N + 63) / 64, (M + 127) / 128);
    hgemm<<<g, 256, SMEM_DYN, st>>>(Ah, Al, ldA, Bh, ldB, bias, C, ldc, M, N, K, act);
}

extern "C" void kernel_launch(void* const* d_in, const int* in_sizes, int n_in,
                              void* d_out, int out_size) {
    const float* feats   = (const float*)d_in[0];
    const int*   tokens  = (const int*)d_in[1];
    const int*   src     = (const int*)d_in[2];
    const int*   dst     = (const int*)d_in[3];
    const int*   etype   = (const int*)d_in[4];
    const int*   batch   = (const int*)d_in[5];
    const float* embed_w = (const float*)d_in[6];
    const float* ggnn_W  = (const float*)d_in[7];
    const float* ggnn_b  = (const float*)d_in[8];
    const float* Wih     = (const float*)d_in[9];
    const float* Whh     = (const float*)d_in[10];
    const float* bih     = (const float*)d_in[11];
    const float* bhh     = (const float*)d_in[12];
    const float* gWih    = (const float*)d_in[13];
    const float* gWhh    = (const float*)d_in[14];
    const float* gbih    = (const float*)d_in[15];
    const float* gbhh    = (const float*)d_in[16];
    const float* l1W = (const float*)d_in[17]; const float* l1b = (const float*)d_in[18];
    const float* l11W = (const float*)d_in[19]; const float* l11b = (const float*)d_in[20];
    const float* l2W = (const float*)d_in[21]; const float* l2b = (const float*)d_in[22];
    float* out = (float*)d_out;

    static bool sinit = false;
    static cudaStream_t s1;
    static cudaEvent_t eF, eJ;
    if (!sinit) {
        cudaFuncSetAttribute(hgemm, cudaFuncAttributeMaxDynamicSharedMemorySize, SMEM_DYN);
        cudaStreamCreateWithFlags(&s1, cudaStreamNonBlocking);
        cudaEventCreateWithFlags(&eF, cudaEventDisableTiming);
        cudaEventCreateWithFlags(&eJ, cudaEventDisableTiming);
        sinit = true;
    }

    float *p_h, *p_tg, *p_gi, *p_gt, *p_WT, *p_f1, *p_f2, *p_bc;
    int *p_off, *p_cnt, *p_csr, *p_boff;
    __half *hh, *hl, *ah, *al, *Wch, *Wihh, *gWh;
    __half *l1h, *l11h, *xh, *xl, *x2h, *x2l, *ch, *cl, *f1h, *f1l;
    SYMP(p_h, g_h);   SYMP(p_tg, g_tg); SYMP(p_gi, g_gi);
    SYMP(p_off, g_off); SYMP(p_cnt, g_cnt); SYMP(p_csr, g_csr); SYMP(p_boff, g_boff);
    SYMP(p_gt, g_gt); SYMP(p_WT, g_WT); SYMP(p_f1, g_f1); SYMP(p_f2, g_f2); SYMP(p_bc, g_bc);
    SYMP(hh, g_hh); SYMP(hl, g_hl); SYMP(ah, g_ah); SYMP(al, g_al);
    SYMP(Wch, g_Wch); SYMP(Wihh, g_Wihh); SYMP(gWh, g_gWh);
    SYMP(l1h, g_l1h); SYMP(l11h, g_l11h);
    SYMP(xh, g_xh); SYMP(xl, g_xl); SYMP(x2h, g_x2h); SYMP(x2l, g_x2l);
    SYMP(ch, g_ch); SYMP(cl, g_cl); SYMP(f1h, g_f1h); SYMP(f1l, g_f1l);

    // fork event (token branch depends only on inputs)
    cudaEventRecord(eF, 0);

    // ---- launch idx 0,1 prep; idx 2 AND 3 are hgemm (ncu target) ----
    k_splitfeats<<<(2000 * 2048 + 255) / 256, 256>>>(feats, hh, hl);
    k_splitWc<<<(10000 * 2048 + 255) / 256, 256>>>(ggnn_W, Whh, ggnn_b, bhh, Wch, p_bc);
    tcg(0, hh, hl, 2048, Wch, 2048, p_bc, p_tg, 10000, NN, 5000, 128, 0);
    tcg(0, hh, hl, 2048, Wch + (size_t)5000 * 2048, 2048,
        p_bc + 5000, p_tg + 5000, 10000, NN, 5000, 128, 0);
    k_hinit<<<(NN * HH + 255) / 256, 256>>>(feats, p_h);

    // CSR + batch offsets
    k_zero_int<<<(NN + 255) / 256, 256>>>(p_cnt, NN);
    k_count<<<(EE + 255) / 256, 256>>>(dst, p_cnt);
    k_scan<<<1, 1024>>>(p_cnt, p_off);
    k_zero_int<<<(NN + 255) / 256, 256>>>(p_cnt, NN);
    k_fill<<<(EE + 255) / 256, 256>>>(src, dst, etype, p_off, p_cnt, p_csr);
    k_boff<<<(NN + 255) / 256, 256>>>(batch, p_boff);

    // B-side weight conversions (hi only)
    k_tohalf<<<(6000 * 2048 + 255) / 256, 256>>>(Wih, Wihh, 6000, 2000, 2048);
    k_tohalf<<<(1000 * 3200 + 255) / 256, 256>>>(l1W, l1h, 1000, 3200, 3200);
    k_tohalf<<<(500 * 1024 + 255) / 256, 256>>>(l11W, l11h, 500, 1000, 1024);

    // ---- GGNN steps ----
    for (int step = 0; step < 3; step++) {
        if (step > 0)
            tcg(0, hh, hl, 2048, Wch, 2048, p_bc, p_tg, 10000, NN, 10000, 2048, 0);
        k_agg<<<dim3(NN, 8), 256>>>(p_tg, p_off, p_csr, ah, al);
        tcg(0, ah, al, 2048, Wihh, 2048, bih, p_gi, 6000, NN, 6000, 2048, 0);
        k_cell<<<(NN * HH + 255) / 256, 256>>>(p_gi, p_tg, p_h, hh, hl);
    }
    k_segmax<<<dim3(8, BB), 256>>>(p_h, p_boff, ch, cl);

    // ---- token branch on s1 (forked; joins before head) ----
    cudaStreamWaitEvent(s1, eF, 0);
    k_embed<<<LL * BB, 128, 0, s1>>>(embed_w, tokens, xh, xl);
    k_zpad<<<(4096 * 48 + 255) / 256, 256, 0, s1>>>(x2h, x2l);
    k_transpose_whh<<<(6 * 600 * 200 + 255) / 256, 256, 0, s1>>>(gWhh, p_WT);
    k_tohalf<<<(3600 * 448 + 255) / 256, 256, 0, s1>>>(gWih, gWh, 3600, 400, 448);

    __half* inh = xh;  __half* inl = xl;
    __half* outh = x2h; __half* outl = x2l;
    for (int l = 0; l < 3; l++) {
        tcg(s1, inh, inl, 448, gWh + (size_t)l * 1200 * 448, 448,
            gbih + l * 1200, p_gt, 1200, LL * BB, 1200, 448, 0);
        k_gruscan<<<16, 256, 0, s1>>>(p_gt, p_WT + l * 240000, gbhh + l * 1200,
                                      outh, outl, ch, cl, l);
        __half* t1 = inh; inh = outh; outh = t1;
        __half* t2 = inl; inl = outl; outl = t2;
    }
    cudaEventRecord(eJ, s1);
    cudaStreamWaitEvent(0, eJ, 0);

    // ---- head (needs both branches) ----
    tcg(0, ch, cl, 3200, l1h, 3200, l1b, p_f1, 1000, BB, 1000, 3200, 1);
    k_split<<<(16 * 1024 + 255) / 256, 256>>>(p_f1, f1h, f1l, BB, 1000, 1024);
    tcg(0, f1h, f1l, 1024, l11h, 1024, l11b, p_f2, 500, BB, 500, 1024, 1);
    k_head2<<<1, 32>>>(p_f2, l2W, l2b, out);

    (void)in_sizes; (void)n_in; (void)out_size;
}

// round 14
// speedup vs baseline: 1.5264x; 1.5264x over previous
#include <cuda_runtime.h>
#include <cuda_fp16.h>
#include <stdint.h>
#include <math.h>

#define NN 2000
#define EE 16000
#define BB 16
#define LL 256
#define HH 2000
#define FIN 100
#define GG 200

// ---------------- scratch (device globals; no cudaMalloc allowed) ----------------
__device__ float g_h[(size_t)NN * HH];
__device__ float g_tg[(size_t)NN * 10000];      // combined [etype(4000) | gh(6000)]
__device__ float g_gi[(size_t)NN * 3 * HH];
__device__ int   g_off[NN + 1];
__device__ int   g_cnt[NN];
__device__ int   g_csr[EE];
__device__ int   g_boff[BB + 1];
__device__ float g_gt[(size_t)LL * BB * 1200];
__device__ float g_f1[BB * 1000];
__device__ float g_f2[BB * 500];
__device__ float g_bc[10000];

// fp16 operand buffers: A-side hi+lo, B-side (weights) hi only
__device__ __half g_hh[(size_t)2000 * 2048], g_hl[(size_t)2000 * 2048];
__device__ __half g_ah[(size_t)2000 * 2048], g_al[(size_t)2000 * 2048];
__device__ __half g_Wch[(size_t)10000 * 2048];
__device__ __half g_Wihh[(size_t)6000 * 2048];
__device__ __half g_gWh[(size_t)3600 * 448];
__device__ __half g_l1h[(size_t)1000 * 3200];
__device__ __half g_l11h[(size_t)500 * 1024];
__device__ __half g_WTh[3 * 2 * 200 * 600];     // gruscan Whh^T fp16
__device__ __half g_xh[(size_t)4096 * 448], g_xl[(size_t)4096 * 448];
__device__ __half g_x2h[(size_t)4096 * 448], g_x2l[(size_t)4096 * 448];
__device__ __half g_ch[(size_t)16 * 3200], g_cl[(size_t)16 * 3200];
__device__ __half g_f1h[(size_t)16 * 1024], g_f1l[(size_t)16 * 1024];

// ---------------- small helpers ----------------
__device__ __forceinline__ float sigm(float x) { return 1.f / (1.f + expf(-x)); }
__device__ __forceinline__ void splitw(float v, __half& h, __half& l) {
    h = __float2half_rn(v);
    l = __float2half_rn(v - __half2float(h));
}
__device__ __forceinline__ uint32_t s2u(const void* p) {
    uint32_t a;
    asm("{ .reg .u64 t; cvta.to.shared.u64 t, %1; cvt.u32.u64 %0, t; }" : "=r"(a) : "l"(p));
    return a;
}
__device__ __forceinline__ void cpa16(uint32_t dst, const void* src, uint32_t sz) {
    asm volatile("cp.async.ca.shared.global [%0], [%1], 16, %2;" :: "r"(dst), "l"(src), "r"(sz));
}
__device__ __forceinline__ void ldm4(uint32_t* r, uint32_t addr) {
    asm volatile("ldmatrix.sync.aligned.m8n8.x4.shared.b16 {%0,%1,%2,%3}, [%4];"
                 : "=r"(r[0]), "=r"(r[1]), "=r"(r[2]), "=r"(r[3]) : "r"(addr));
}
__device__ __forceinline__ void hmma(float* c, const uint32_t* a, const uint32_t* b) {
    asm volatile("mma.sync.aligned.m16n8k16.row.col.f32.f16.f16.f32 "
                 "{%0,%1,%2,%3},{%4,%5,%6,%7},{%8,%9},{%0,%1,%2,%3};"
                 : "+f"(c[0]), "+f"(c[1]), "+f"(c[2]), "+f"(c[3])
                 : "r"(a[0]), "r"(a[1]), "r"(a[2]), "r"(a[3]), "r"(b[0]), "r"(b[1]));
}

// ============ fp16 2-term split GEMM: C = act((Ah+Al) @ Bh^T + bias) ============
// CTA tile 128(M) x 64(N), 256 threads, K-chunk 64, RS=144, double-buffered,
// 2 CTAs co-resident per SM.
#define RS 144
#define MATAB (128 * RS)
#define MATBB (64 * RS)
#define BUFB (2 * MATAB + MATBB)
#define SMEM_DYN (2 * BUFB)

__global__ __launch_bounds__(256, 2) void hgemm(
    const __half* __restrict__ Ah, const __half* __restrict__ Al, int ldA,
    const __half* __restrict__ Bh, int ldB,
    const float* __restrict__ bias, float* __restrict__ C, int ldc,
    int M, int N, int K, int act)
{
    extern __shared__ char smem[];
    const uint32_t sb = s2u(smem);
    const int tid = threadIdx.x;
    const int warp = tid >> 5, lane = tid & 31;
    const int wm = warp & 3, wn = warp >> 2;
    const int br = blockIdx.y * 128, bc = blockIdx.x * 64;
    const int nk = K >> 6;

    float acc[2][4][4];
#pragma unroll
    for (int mt = 0; mt < 2; mt++)
#pragma unroll
        for (int nt = 0; nt < 4; nt++)
#pragma unroll
            for (int r = 0; r < 4; r++) acc[mt][nt][r] = 0.f;

    auto issue = [&](int c) {
        uint32_t tb = sb + (uint32_t)(c & 1) * BUFB;
        int k0 = c << 6;
#pragma unroll
        for (int i = 0; i < 10; i++) {
            int g = (i << 8) + tid;
            if (g < 2048) {
                int which = g >> 10;
                int row = (g >> 3) & 127;
                int kb = g & 7;
                uint32_t dst = tb + which * MATAB + row * RS + kb * 16;
                int gr = br + row;
                const __half* base = which ? Al : Ah;
                uint32_t sz = (gr < M) ? 16u : 0u;
                cpa16(dst, base + (size_t)(gr < M ? gr : 0) * ldA + k0 + kb * 8, sz);
            } else {
                int g2 = g - 2048;
                int row = g2 >> 3;
                int kb = g2 & 7;
                uint32_t dst = tb + 2 * MATAB + row * RS + kb * 16;
                int gn = bc + row;
                uint32_t sz = (gn < N) ? 16u : 0u;
                cpa16(dst, Bh + (size_t)(gn < N ? gn : 0) * ldB + k0 + kb * 8, sz);
            }
        }
        asm volatile("cp.async.commit_group;");
    };

    const int arow = wm * 32 + (lane & 15);
    const int ak = (lane >> 4);
    const int brow = wn * 32 + (lane & 7) + ((lane >> 4) << 3);
    const int bk = ((lane >> 3) & 1);

    auto compute = [&](int c) {
        uint32_t tb = sb + (uint32_t)(c & 1) * BUFB;
        uint32_t aAh = tb, aAl = tb + MATAB, aBh = tb + 2 * MATAB;
#pragma unroll
        for (int k16 = 0; k16 < 4; k16++) {
            uint32_t ah[2][4], al[2][4];
#pragma unroll
            for (int mt = 0; mt < 2; mt++) {
                uint32_t off = (uint32_t)(arow + mt * 16) * RS + (2 * k16 + ak) * 16;
                ldm4(ah[mt], aAh + off);
                ldm4(al[mt], aAl + off);
            }
            uint32_t bh[4][2];
#pragma unroll
            for (int np = 0; np < 2; np++) {
                uint32_t off = (uint32_t)(brow + np * 16) * RS + (2 * k16 + bk) * 16;
                uint32_t t4[4];
                ldm4(t4, aBh + off);
                bh[np * 2][0] = t4[0]; bh[np * 2][1] = t4[1];
                bh[np * 2 + 1][0] = t4[2]; bh[np * 2 + 1][1] = t4[3];
            }
#pragma unroll
            for (int mt = 0; mt < 2; mt++)
#pragma unroll
                for (int nt = 0; nt < 4; nt++) {
                    hmma(acc[mt][nt], ah[mt], bh[nt]);
                    hmma(acc[mt][nt], al[mt], bh[nt]);
                }
        }
    };

    issue(0);
    for (int c = 0; c < nk; c++) {
        if (c + 1 < nk) {
            issue(c + 1);
            asm volatile("cp.async.wait_group 1;" ::: "memory");
        } else {
            asm volatile("cp.async.wait_group 0;" ::: "memory");
        }
        __syncthreads();
        compute(c);
        __syncthreads();
    }

#pragma unroll
    for (int mt = 0; mt < 2; mt++) {
        int row0 = br + wm * 32 + mt * 16 + (lane >> 2);
#pragma unroll
        for (int nt = 0; nt < 4; nt++) {
            int col = bc + wn * 32 + nt * 8 + ((lane & 3) << 1);
            if (col < N) {
                float b0 = bias ? bias[col] : 0.f;
                float b1 = bias ? bias[col + 1] : 0.f;
#pragma unroll
                for (int hi = 0; hi < 2; hi++) {
                    int row = row0 + hi * 8;
                    if (row < M) {
                        float2 v;
                        v.x = acc[mt][nt][hi * 2] + b0;
                        v.y = acc[mt][nt][hi * 2 + 1] + b1;
                        if (act) { v.x = fmaxf(v.x, 0.f); v.y = fmaxf(v.y, 0.f); }
                        *reinterpret_cast<float2*>(C + (size_t)row * ldc + col) = v;
                    }
                }
            }
        }
    }
}

// ---------------- split / convert kernels ----------------
__global__ void k_split(const float* __restrict__ in, __half* __restrict__ oh,
                        __half* __restrict__ ol, int R, int K, int Kp) {
    int idx = blockIdx.x * blockDim.x + threadIdx.x;
    if (idx >= R * Kp) return;
    int r = idx / Kp, c = idx - r * Kp;
    float v = (c < K) ? in[(size_t)r * K + c] : 0.f;
    splitw(v, oh[idx], ol[idx]);
}
__global__ void k_tohalf(const float* __restrict__ in, __half* __restrict__ oh,
                         int R, int K, int Kp) {
    int idx = blockIdx.x * blockDim.x + threadIdx.x;
    if (idx >= R * Kp) return;
    int r = idx / Kp, c = idx - r * Kp;
    float v = (c < K) ? in[(size_t)r * K + c] : 0.f;
    oh[idx] = __float2half_rn(v);
}
__global__ void k_splitfeats(const float* __restrict__ feats, __half* __restrict__ oh,
                             __half* __restrict__ ol) {
    int idx = blockIdx.x * blockDim.x + threadIdx.x;
    if (idx >= 2000 * 2048) return;
    int r = idx >> 11, c = idx & 2047;
    float v = (c < FIN) ? feats[r * FIN + c] : 0.f;
    splitw(v, oh[idx], ol[idx]);
}
__global__ void k_splitWc(const float* __restrict__ Wg, const float* __restrict__ Whh,
                          const float* __restrict__ bg, const float* __restrict__ bhh,
                          __half* __restrict__ oh, float* __restrict__ bc) {
    int idx = blockIdx.x * blockDim.x + threadIdx.x;
    if (idx >= 10000 * 2048) return;
    int r = idx >> 11, c = idx & 2047;
    float v = 0.f;
    if (c < 2000) v = (r < 4000) ? Wg[(size_t)r * 2000 + c] : Whh[(size_t)(r - 4000) * 2000 + c];
    oh[idx] = __float2half_rn(v);
    if (idx < 10000) bc[idx] = (idx < 4000) ? bg[idx] : bhh[idx - 4000];
}

// ---------------- CSR build ----------------
__global__ void k_zero_int(int* p, int n) {
    int i = blockIdx.x * blockDim.x + threadIdx.x;
    if (i < n) p[i] = 0;
}
__global__ void k_count(const int* __restrict__ dst, int* cnt) {
    int i = blockIdx.x * blockDim.x + threadIdx.x;
    if (i < EE) atomicAdd(&cnt[dst[i]], 1);
}
__global__ void k_scan(const int* __restrict__ cnt, int* __restrict__ off) {
    int tid = threadIdx.x;
    int a = (2 * tid < NN) ? cnt[2 * tid] : 0;
    int b = (2 * tid + 1 < NN) ? cnt[2 * tid + 1] : 0;
    int ts = a + b;
    int lane = tid & 31, wid = tid >> 5;
    int v = ts;
#pragma unroll
    for (int d = 1; d < 32; d <<= 1) {
        int u = __shfl_up_sync(0xffffffffu, v, d);
        if (lane >= d) v += u;
    }
    __shared__ int ws[32];
    if (lane == 31) ws[wid] = v;
    __syncthreads();
    if (wid == 0) {
        int w = ws[lane];
#pragma unroll
        for (int d = 1; d < 32; d <<= 1) {
            int u = __shfl_up_sync(0xffffffffu, w, d);
            if (lane >= d) w += u;
        }
        ws[lane] = w;
    }
    __syncthreads();
    int incl = v + (wid > 0 ? ws[wid - 1] : 0);
    int excl = incl - ts;
    if (2 * tid <= NN) off[2 * tid] = excl;
    if (2 * tid + 1 <= NN) off[2 * tid + 1] = excl + a;
}
__global__ void k_fill(const int* __restrict__ src, const int* __restrict__ dst,
                       const int* __restrict__ et, const int* __restrict__ off,
                       int* cnt, int* __restrict__ csr) {
    int i = blockIdx.x * blockDim.x + threadIdx.x;
    if (i < EE) {
        int d = dst[i];
        int p = off[d] + atomicAdd(&cnt[d], 1);
        csr[p] = src[i] * 2 + et[i];
    }
}
__global__ void k_boff(const int* __restrict__ batch, int* boff) {
    int i = blockIdx.x * blockDim.x + threadIdx.x;
    if (i >= NN) return;
    int b = batch[i];
    if (i == 0) {
        for (int x = 0; x <= b; x++) boff[x] = 0;
    } else {
        int pb = batch[i - 1];
        if (pb != b) for (int x = pb + 1; x <= b; x++) boff[x] = i;
    }
    if (i == NN - 1) {
        for (int x = b + 1; x <= BB; x++) boff[x] = NN;
    }
}

// ---------------- GGNN pieces (fused splits) ----------------
__global__ void k_hinit(const float* __restrict__ feats, float* __restrict__ h) {
    int i = blockIdx.x * blockDim.x + threadIdx.x;
    if (i >= NN * HH) return;
    int r = i / HH, c = i % HH;
    h[i] = (c < FIN) ? feats[r * FIN + c] : 0.f;
}
__global__ void k_agg(const float* __restrict__ tg, const int* __restrict__ off,
                      const int* __restrict__ csr, __half* __restrict__ ah,
                      __half* __restrict__ al) {
    int d = blockIdx.x;
    int j = blockIdx.y * 256 + threadIdx.x;
    size_t o = (size_t)d * 2048 + j;
    if (j >= 2000) { ah[o] = __half(0.f); al[o] = __half(0.f); return; }
    int s0 = off[d], s1 = off[d + 1];
    float acc = 0.f;
    for (int p = s0; p < s1; p++) {
        int v = csr[p];
        int sn = v >> 1, e = v & 1;
        acc += tg[(size_t)sn * 10000 + e * 2000 + j];
    }
    splitw(acc, ah[o], al[o]);
}
__global__ void k_cell(const float* __restrict__ gi, const float* __restrict__ tg,
                       float* __restrict__ h, __half* __restrict__ hh,
                       __half* __restrict__ hl) {
    int i = blockIdx.x * blockDim.x + threadIdx.x;
    if (i >= NN * HH) return;
    int r = i / HH, c = i % HH;
    size_t gI = (size_t)r * 6000 + c;
    size_t gH = (size_t)r * 10000 + 4000 + c;
    float rr = sigm(gi[gI] + tg[gH]);
    float zz = sigm(gi[gI + 2000] + tg[gH + 2000]);
    float nn = tanhf(gi[gI + 4000] + rr * tg[gH + 4000]);
    float hv = (1.f - zz) * nn + zz * h[i];
    h[i] = hv;
    size_t o = (size_t)r * 2048 + c;
    splitw(hv, hh[o], hl[o]);
}
__global__ void k_segmax(const float* __restrict__ h, const int* __restrict__ boff,
                         __half* __restrict__ ch, __half* __restrict__ cl) {
    int b = blockIdx.y;
    int j = blockIdx.x * 256 + threadIdx.x;
    if (j >= HH) return;
    int s = boff[b], e = boff[b + 1];
    float m = -INFINITY;
    for (int i = s; i < e; i++) m = fmaxf(m, h[(size_t)i * HH + j]);
    splitw(m, ch[b * 3200 + j], cl[b * 3200 + j]);
}

// ---------------- token branch ----------------
__global__ void k_embed(const float* __restrict__ ew, const int* __restrict__ tokens,
                        __half* __restrict__ xh, __half* __restrict__ xl) {
    int tb = blockIdx.x;
    int t = tb / BB, b = tb % BB;
    int tok = tokens[b * LL + t];
    size_t ro = (size_t)tb * 448;
    for (int j = threadIdx.x; j < 448; j += blockDim.x) {
        float v = (j < FIN) ? ew[(size_t)tok * FIN + j] : 0.f;
        splitw(v, xh[ro + j], xl[ro + j]);
    }
}
__global__ void k_zpad(__half* __restrict__ xh, __half* __restrict__ xl) {
    int idx = blockIdx.x * blockDim.x + threadIdx.x;
    if (idx >= 4096 * 48) return;
    int r = idx / 48, c = 400 + idx % 48;
    xh[(size_t)r * 448 + c] = __half(0.f);
    xl[(size_t)r * 448 + c] = __half(0.f);
}
// W [6][600][200] fp32 -> WTh [6][200][600] fp16
__global__ void k_transpose_whh(const float* __restrict__ W, __half* __restrict__ WT) {
    int i = blockIdx.x * blockDim.x + threadIdx.x;
    if (i >= 6 * 600 * 200) return;
    int ld = i / (600 * 200);
    int rem = i % (600 * 200);
    int j = rem / 200, k = rem % 200;
    WT[ld * 120000 + k * 600 + j] = __float2half_rn(W[i]);
}

// GRU scan v2: fp16 W (uint4 = 8 j's per load), 8 k-slabs of 25 fully unrolled,
// gi prefetched into registers one step ahead. One CTA per (dir, batch-pair).
__global__ __launch_bounds__(256) void k_gruscan(
    const float* __restrict__ giAll,
    const __half* __restrict__ WTl,      // [2][200][600] fp16
    const float* __restrict__ bhhl,
    __half* __restrict__ yh, __half* __restrict__ yl,   // [L*B][448]
    __half* __restrict__ ch, __half* __restrict__ cl,
    int layer)
{
    int cid = blockIdx.x;
    int dir = cid & 1;
    int bp = cid >> 1;
    const __half* W = WTl + dir * 120000;
    const float* bhh = bhhl + dir * 600;

    __shared__ float sh_h[2][200];
    __shared__ float sh_gi[1200];
    __shared__ float red[8][2][3][200];

    int tid = threadIdx.x;
    int ks = tid >> 5;        // 0..7, k-slab of 25
    int jg = tid & 31;        // active < 25, 8 j's each

    for (int i = tid; i < 400; i += 256) (&sh_h[0][0])[i] = 0.f;

    // preload gi for step 0 into registers
    float rg[5];
    {
        int t0 = dir ? (LL - 1) : 0;
        const float* g0 = giAll + ((size_t)(t0 * BB + 2 * bp)) * 1200 + dir * 600;
#pragma unroll
        for (int q = 0; q < 5; q++) {
            int i = tid + q * 256;
            rg[q] = (i < 1200) ? ((i < 600) ? g0[i] : g0[1200 + (i - 600)]) : 0.f;
        }
    }
    __syncthreads();

    for (int s = 0; s < LL; s++) {
        // commit staged gi to smem
#pragma unroll
        for (int q = 0; q < 5; q++) {
            int i = tid + q * 256;
            if (i < 1200) sh_gi[i] = rg[q];
        }
        __syncthreads();

        // stage next step's gi (latency overlaps matvec)
        if (s + 1 < LL) {
            int tn = dir ? (LL - 2 - s) : (s + 1);
            const float* gn = giAll + ((size_t)(tn * BB + 2 * bp)) * 1200 + dir * 600;
#pragma unroll
            for (int q = 0; q < 5; q++) {
                int i = tid + q * 256;
                rg[q] = (i < 1200) ? ((i < 600) ? gn[i] : gn[1200 + (i - 600)]) : 0.f;
            }
        }

        // matvec partials: thread (ks, jg<25) covers k in [ks*25,ks*25+25), j in [jg*8, jg*8+8)
        if (jg < 25) {
            float acc[2][3][8];
#pragma unroll
            for (int b = 0; b < 2; b++)
#pragma unroll
                for (int g = 0; g < 3; g++)
#pragma unroll
                    for (int jj = 0; jj < 8; jj++) acc[b][g][jj] = 0.f;
            int kb = ks * 25;
#pragma unroll
            for (int kk = 0; kk < 25; kk++) {
                int k = kb + kk;
                float h0 = sh_h[0][k];
                float h1 = sh_h[1][k];
                const __half* row = W + k * 600;
#pragma unroll
                for (int g = 0; g < 3; g++) {
                    uint4 u = *reinterpret_cast<const uint4*>(row + g * 200 + jg * 8);
                    float2 f0 = __half22float2(*reinterpret_cast<__half2*>(&u.x));
                    float2 f1 = __half22float2(*reinterpret_cast<__half2*>(&u.y));
                    float2 f2 = __half22float2(*reinterpret_cast<__half2*>(&u.z));
                    float2 f3 = __half22float2(*reinterpret_cast<__half2*>(&u.w));
                    float wv[8] = {f0.x, f0.y, f1.x, f1.y, f2.x, f2.y, f3.x, f3.y};
#pragma unroll
                    for (int jj = 0; jj < 8; jj++) {
                        acc[0][g][jj] += wv[jj] * h0;
                        acc[1][g][jj] += wv[jj] * h1;
                    }
                }
            }
#pragma unroll
            for (int b = 0; b < 2; b++)
#pragma unroll
                for (int g = 0; g < 3; g++)
#pragma unroll
                    for (int jj = 0; jj < 8; jj++)
                        red[ks][b][g][jg * 8 + jj] = acc[b][g][jj];
        }
        __syncthreads();

        // cell update: thread j<200 handles both batches
        if (tid < 200) {
            int j = tid;
            int t = dir ? (LL - 1 - s) : s;
#pragma unroll
            for (int b = 0; b < 2; b++) {
                float gr = 0.f, gz = 0.f, gn2 = 0.f;
#pragma unroll
                for (int ki = 0; ki < 8; ki++) {
                    gr += red[ki][b][0][j];
                    gz += red[ki][b][1][j];
                    gn2 += red[ki][b][2][j];
                }
                gr += bhh[j]; gz += bhh[200 + j]; gn2 += bhh[400 + j];
                float rr = sigm(sh_gi[b * 600 + j] + gr);
                float zz = sigm(sh_gi[b * 600 + 200 + j] + gz);
                float nn = tanhf(sh_gi[b * 600 + 400 + j] + rr * gn2);
                float hnew = (1.f - zz) * nn + zz * sh_h[b][j];
                int gb = 2 * bp + b;
                size_t yo = ((size_t)(t * BB + gb)) * 448 + dir * 200 + j;
                __half hh_ = __float2half_rn(hnew);
                __half hl_ = __float2half_rn(hnew - __half2float(hh_));
                yh[yo] = hh_; yl[yo] = hl_;
                if (s == LL - 1) {
                    size_t co = (size_t)gb * 3200 + 2000 + (2 * layer + dir) * 200 + j;
                    ch[co] = hh_; cl[co] = hl_;
                }
                sh_h[b][j] = hnew;
            }
        }
        __syncthreads();
    }
}

// ---------------- final tiny head layer (N=2) ----------------
__global__ void k_head2(const float* __restrict__ f2, const float* __restrict__ W,
                        const float* __restrict__ b, float* __restrict__ out) {
    int t = threadIdx.x;
    if (t >= 32) return;
    int bb = t >> 1, n = t & 1;
    float acc = 0.f;
    for (int k = 0; k < 500; k++) acc += f2[bb * 500 + k] * W[n * 500 + k];
    out[bb * 2 + n] = fmaxf(acc + b[n], 0.f);
}

// ---------------- host side ----------------
#define SYMP(p, s) do { void* _q = nullptr; cudaGetSymbolAddress(&_q, s); p = (decltype(p))_q; } while (0)

static void tcg(cudaStream_t st, const __half* Ah, const __half* Al, int ldA,
                const __half* Bh, int ldB,
                const float* bias, float* C, int ldc, int M, int N, int K, int act) {
    dim3 g((N + 63) / 64, (M + 127) / 128);
    hgemm<<<g, 256, SMEM_DYN, st>>>(Ah, Al, ldA, Bh, ldB, bias, C, ldc, M, N, K, act);
}

extern "C" void kernel_launch(void* const* d_in, const int* in_sizes, int n_in,
                              void* d_out, int out_size) {
    const float* feats   = (const float*)d_in[0];
    const int*   tokens  = (const int*)d_in[1];
    const int*   src     = (const int*)d_in[2];
    const int*   dst     = (const int*)d_in[3];
    const int*   etype   = (const int*)d_in[4];
    const int*   batch   = (const int*)d_in[5];
    const float* embed_w = (const float*)d_in[6];
    const float* ggnn_W  = (const float*)d_in[7];
    const float* ggnn_b  = (const float*)d_in[8];
    const float* Wih     = (const float*)d_in[9];
    const float* Whh     = (const float*)d_in[10];
    const float* bih     = (const float*)d_in[11];
    const float* bhh     = (const float*)d_in[12];
    const float* gWih    = (const float*)d_in[13];
    const float* gWhh    = (const float*)d_in[14];
    const float* gbih    = (const float*)d_in[15];
    const float* gbhh    = (const float*)d_in[16];
    const float* l1W = (const float*)d_in[17]; const float* l1b = (const float*)d_in[18];
    const float* l11W = (const float*)d_in[19]; const float* l11b = (const float*)d_in[20];
    const float* l2W = (const float*)d_in[21]; const float* l2b = (const float*)d_in[22];
    float* out = (float*)d_out;

    static bool sinit = false;
    static cudaStream_t s1;
    static cudaEvent_t eF, eJ;
    if (!sinit) {
        cudaFuncSetAttribute(hgemm, cudaFuncAttributeMaxDynamicSharedMemorySize, SMEM_DYN);
        cudaStreamCreateWithFlags(&s1, cudaStreamNonBlocking);
        cudaEventCreateWithFlags(&eF, cudaEventDisableTiming);
        cudaEventCreateWithFlags(&eJ, cudaEventDisableTiming);
        sinit = true;
    }

    float *p_h, *p_tg, *p_gi, *p_gt, *p_f1, *p_f2, *p_bc;
    int *p_off, *p_cnt, *p_csr, *p_boff;
    __half *hh, *hl, *ah, *al, *Wch, *Wihh, *gWh, *p_WTh;
    __half *l1h, *l11h, *xh, *xl, *x2h, *x2l, *ch, *cl, *f1h, *f1l;
    SYMP(p_h, g_h);   SYMP(p_tg, g_tg); SYMP(p_gi, g_gi);
    SYMP(p_off, g_off); SYMP(p_cnt, g_cnt); SYMP(p_csr, g_csr); SYMP(p_boff, g_boff);
    SYMP(p_gt, g_gt); SYMP(p_f1, g_f1); SYMP(p_f2, g_f2); SYMP(p_bc, g_bc);
    SYMP(hh, g_hh); SYMP(hl, g_hl); SYMP(ah, g_ah); SYMP(al, g_al);
    SYMP(Wch, g_Wch); SYMP(Wihh, g_Wihh); SYMP(gWh, g_gWh); SYMP(p_WTh, g_WTh);
    SYMP(l1h, g_l1h); SYMP(l11h, g_l11h);
    SYMP(xh, g_xh); SYMP(xl, g_xl); SYMP(x2h, g_x2h); SYMP(x2l, g_x2l);
    SYMP(ch, g_ch); SYMP(cl, g_cl); SYMP(f1h, g_f1h); SYMP(f1l, g_f1l);

    // fork event (token branch depends only on inputs)
    cudaEventRecord(eF, 0);

    // ---- GGNN prep + first GEMMs ----
    k_splitfeats<<<(2000 * 2048 + 255) / 256, 256>>>(feats, hh, hl);
    k_splitWc<<<(10000 * 2048 + 255) / 256, 256>>>(ggnn_W, Whh, ggnn_b, bhh, Wch, p_bc);
    tcg(0, hh, hl, 2048, Wch, 2048, p_bc, p_tg, 10000, NN, 5000, 128, 0);
    tcg(0, hh, hl, 2048, Wch + (size_t)5000 * 2048, 2048,
        p_bc + 5000, p_tg + 5000, 10000, NN, 5000, 128, 0);
    k_hinit<<<(NN * HH + 255) / 256, 256>>>(feats, p_h);

    // CSR + batch offsets
    k_zero_int<<<(NN + 255) / 256, 256>>>(p_cnt, NN);
    k_count<<<(EE + 255) / 256, 256>>>(dst, p_cnt);
    k_scan<<<1, 1024>>>(p_cnt, p_off);
    k_zero_int<<<(NN + 255) / 256, 256>>>(p_cnt, NN);
    k_fill<<<(EE + 255) / 256, 256>>>(src, dst, etype, p_off, p_cnt, p_csr);
    k_boff<<<(NN + 255) / 256, 256>>>(batch, p_boff);

    // B-side weight conversions (hi only)
    k_tohalf<<<(6000 * 2048 + 255) / 256, 256>>>(Wih, Wihh, 6000, 2000, 2048);
    k_tohalf<<<(1000 * 3200 + 255) / 256, 256>>>(l1W, l1h, 1000, 3200, 3200);
    k_tohalf<<<(500 * 1024 + 255) / 256, 256>>>(l11W, l11h, 500, 1000, 1024);

    // ---- GGNN steps ----
    for (int step = 0; step < 3; step++) {
        if (step > 0)
            tcg(0, hh, hl, 2048, Wch, 2048, p_bc, p_tg, 10000, NN, 10000, 2048, 0);
        k_agg<<<dim3(NN, 8), 256>>>(p_tg, p_off, p_csr, ah, al);
        tcg(0, ah, al, 2048, Wihh, 2048, bih, p_gi, 6000, NN, 6000, 2048, 0);
        k_cell<<<(NN * HH + 255) / 256, 256>>>(p_gi, p_tg, p_h, hh, hl);
    }
    k_segmax<<<dim3(8, BB), 256>>>(p_h, p_boff, ch, cl);

    // ---- token branch on s1 (forked; joins before head) ----
    cudaStreamWaitEvent(s1, eF, 0);
    k_embed<<<LL * BB, 128, 0, s1>>>(embed_w, tokens, xh, xl);
    k_zpad<<<(4096 * 48 + 255) / 256, 256, 0, s1>>>(x2h, x2l);
    k_transpose_whh<<<(6 * 600 * 200 + 255) / 256, 256, 0, s1>>>(gWhh, p_WTh);
    k_tohalf<<<(3600 * 448 + 255) / 256, 256, 0, s1>>>(gWih, gWh, 3600, 400, 448);

    __half* inh = xh;  __half* inl = xl;
    __half* outh = x2h; __half* outl = x2l;
    for (int l = 0; l < 3; l++) {
        tcg(s1, inh, inl, 448, gWh + (size_t)l * 1200 * 448, 448,
            gbih + l * 1200, p_gt, 1200, LL * BB, 1200, 448, 0);
        k_gruscan<<<16, 256, 0, s1>>>(p_gt, p_WTh + l * 240000, gbhh + l * 1200,
                                      outh, outl, ch, cl, l);
        __half* t1 = inh; inh = outh; outh = t1;
        __half* t2 = inl; inl = outl; outl = t2;
    }
    cudaEventRecord(eJ, s1);
    cudaStreamWaitEvent(0, eJ, 0);

    // ---- head (needs both branches) ----
    tcg(0, ch, cl, 3200, l1h, 3200, l1b, p_f1, 1000, BB, 1000, 3200, 1);
    k_split<<<(16 * 1024 + 255) / 256, 256>>>(p_f1, f1h, f1l, BB, 1000, 1024);
    tcg(0, f1h, f1l, 1024, l11h, 1024, l11b, p_f2, 500, BB, 500, 1024, 1);
    k_head2<<<1, 32>>>(p_f2, l2W, l2b, out);

    (void)in_sizes; (void)n_in; (void)out_size;
}

// round 15
// speedup vs baseline: 2.8620x; 1.8751x over previous
#include <cuda_runtime.h>
#include <cuda_fp16.h>
#include <stdint.h>
#include <math.h>

#define NN 2000
#define EE 16000
#define BB 16
#define LL 256
#define HH 2000
#define FIN 100
#define GG 200

// ---------------- scratch (device globals; no cudaMalloc allowed) ----------------
__device__ float g_h[(size_t)NN * HH];
__device__ float g_tg[(size_t)NN * 10000];      // combined [etype(4000) | gh(6000)]
__device__ float g_gi[(size_t)NN * 3 * HH];
__device__ int   g_off[NN + 1];
__device__ int   g_cnt[NN];
__device__ int   g_csr[EE];
__device__ int   g_boff[BB + 1];
__device__ float g_gt[(size_t)LL * BB * 1200];
__device__ float g_f1[BB * 1000];
__device__ float g_f2[BB * 500];
__device__ float g_bc[10000];

// fp16 operand buffers: A-side hi+lo, B-side (weights) hi only
__device__ __half g_hh[(size_t)2000 * 2048], g_hl[(size_t)2000 * 2048];
__device__ __half g_ah[(size_t)2000 * 2048], g_al[(size_t)2000 * 2048];
__device__ __half g_Wch[(size_t)10000 * 2048];
__device__ __half g_Wihh[(size_t)6000 * 2048];
__device__ __half g_gWh[(size_t)3600 * 448];
__device__ __half g_l1h[(size_t)1000 * 3200];
__device__ __half g_l11h[(size_t)500 * 1024];
__device__ __half g_WTh[3 * 2 * 200 * 600];     // gruscan Whh^T fp16
__device__ __half g_xh[(size_t)4096 * 448], g_xl[(size_t)4096 * 448];
__device__ __half g_x2h[(size_t)4096 * 448], g_x2l[(size_t)4096 * 448];
__device__ __half g_ch[(size_t)16 * 3200], g_cl[(size_t)16 * 3200];
__device__ __half g_f1h[(size_t)16 * 1024], g_f1l[(size_t)16 * 1024];

// ---------------- small helpers ----------------
__device__ __forceinline__ float sigm(float x) { return 1.f / (1.f + expf(-x)); }
__device__ __forceinline__ void splitw(float v, __half& h, __half& l) {
    h = __float2half_rn(v);
    l = __float2half_rn(v - __half2float(h));
}
__device__ __forceinline__ uint32_t s2u(const void* p) {
    uint32_t a;
    asm("{ .reg .u64 t; cvta.to.shared.u64 t, %1; cvt.u32.u64 %0, t; }" : "=r"(a) : "l"(p));
    return a;
}
__device__ __forceinline__ void cpa16(uint32_t dst, const void* src, uint32_t sz) {
    asm volatile("cp.async.ca.shared.global [%0], [%1], 16, %2;" :: "r"(dst), "l"(src), "r"(sz));
}
__device__ __forceinline__ void ldm4(uint32_t* r, uint32_t addr) {
    asm volatile("ldmatrix.sync.aligned.m8n8.x4.shared.b16 {%0,%1,%2,%3}, [%4];"
                 : "=r"(r[0]), "=r"(r[1]), "=r"(r[2]), "=r"(r[3]) : "r"(addr));
}
__device__ __forceinline__ void hmma(float* c, const uint32_t* a, const uint32_t* b) {
    asm volatile("mma.sync.aligned.m16n8k16.row.col.f32.f16.f16.f32 "
                 "{%0,%1,%2,%3},{%4,%5,%6,%7},{%8,%9},{%0,%1,%2,%3};"
                 : "+f"(c[0]), "+f"(c[1]), "+f"(c[2]), "+f"(c[3])
                 : "r"(a[0]), "r"(a[1]), "r"(a[2]), "r"(a[3]), "r"(b[0]), "r"(b[1]));
}

// ============ fp16 2-term split GEMM: C = act((Ah+Al) @ Bh^T + bias) ============
// CTA tile 128(M) x 64(N), 256 threads, K-chunk 64, RS=144, double-buffered,
// 2 CTAs co-resident per SM.
#define RS 144
#define MATAB (128 * RS)
#define MATBB (64 * RS)
#define BUFB (2 * MATAB + MATBB)
#define SMEM_DYN (2 * BUFB)

__global__ __launch_bounds__(256, 2) void hgemm(
    const __half* __restrict__ Ah, const __half* __restrict__ Al, int ldA,
    const __half* __restrict__ Bh, int ldB,
    const float* __restrict__ bias, float* __restrict__ C, int ldc,
    int M, int N, int K, int act)
{
    extern __shared__ char smem[];
    const uint32_t sb = s2u(smem);
    const int tid = threadIdx.x;
    const int warp = tid >> 5, lane = tid & 31;
    const int wm = warp & 3, wn = warp >> 2;
    const int br = blockIdx.y * 128, bc = blockIdx.x * 64;
    const int nk = K >> 6;

    float acc[2][4][4];
#pragma unroll
    for (int mt = 0; mt < 2; mt++)
#pragma unroll
        for (int nt = 0; nt < 4; nt++)
#pragma unroll
            for (int r = 0; r < 4; r++) acc[mt][nt][r] = 0.f;

    auto issue = [&](int c) {
        uint32_t tb = sb + (uint32_t)(c & 1) * BUFB;
        int k0 = c << 6;
#pragma unroll
        for (int i = 0; i < 10; i++) {
            int g = (i << 8) + tid;
            if (g < 2048) {
                int which = g >> 10;
                int row = (g >> 3) & 127;
                int kb = g & 7;
                uint32_t dst = tb + which * MATAB + row * RS + kb * 16;
                int gr = br + row;
                const __half* base = which ? Al : Ah;
                uint32_t sz = (gr < M) ? 16u : 0u;
                cpa16(dst, base + (size_t)(gr < M ? gr : 0) * ldA + k0 + kb * 8, sz);
            } else {
                int g2 = g - 2048;
                int row = g2 >> 3;
                int kb = g2 & 7;
                uint32_t dst = tb + 2 * MATAB + row * RS + kb * 16;
                int gn = bc + row;
                uint32_t sz = (gn < N) ? 16u : 0u;
                cpa16(dst, Bh + (size_t)(gn < N ? gn : 0) * ldB + k0 + kb * 8, sz);
            }
        }
        asm volatile("cp.async.commit_group;");
    };

    const int arow = wm * 32 + (lane & 15);
    const int ak = (lane >> 4);
    const int brow = wn * 32 + (lane & 7) + ((lane >> 4) << 3);
    const int bk = ((lane >> 3) & 1);

    auto compute = [&](int c) {
        uint32_t tb = sb + (uint32_t)(c & 1) * BUFB;
        uint32_t aAh = tb, aAl = tb + MATAB, aBh = tb + 2 * MATAB;
#pragma unroll
        for (int k16 = 0; k16 < 4; k16++) {
            uint32_t ah[2][4], al[2][4];
#pragma unroll
            for (int mt = 0; mt < 2; mt++) {
                uint32_t off = (uint32_t)(arow + mt * 16) * RS + (2 * k16 + ak) * 16;
                ldm4(ah[mt], aAh + off);
                ldm4(al[mt], aAl + off);
            }
            uint32_t bh[4][2];
#pragma unroll
            for (int np = 0; np < 2; np++) {
                uint32_t off = (uint32_t)(brow + np * 16) * RS + (2 * k16 + bk) * 16;
                uint32_t t4[4];
                ldm4(t4, aBh + off);
                bh[np * 2][0] = t4[0]; bh[np * 2][1] = t4[1];
                bh[np * 2 + 1][0] = t4[2]; bh[np * 2 + 1][1] = t4[3];
            }
#pragma unroll
            for (int mt = 0; mt < 2; mt++)
#pragma unroll
                for (int nt = 0; nt < 4; nt++) {
                    hmma(acc[mt][nt], ah[mt], bh[nt]);
                    hmma(acc[mt][nt], al[mt], bh[nt]);
                }
        }
    };

    issue(0);
    for (int c = 0; c < nk; c++) {
        if (c + 1 < nk) {
            issue(c + 1);
            asm volatile("cp.async.wait_group 1;" ::: "memory");
        } else {
            asm volatile("cp.async.wait_group 0;" ::: "memory");
        }
        __syncthreads();
        compute(c);
        __syncthreads();
    }

#pragma unroll
    for (int mt = 0; mt < 2; mt++) {
        int row0 = br + wm * 32 + mt * 16 + (lane >> 2);
#pragma unroll
        for (int nt = 0; nt < 4; nt++) {
            int col = bc + wn * 32 + nt * 8 + ((lane & 3) << 1);
            if (col < N) {
                float b0 = bias ? bias[col] : 0.f;
                float b1 = bias ? bias[col + 1] : 0.f;
#pragma unroll
                for (int hi = 0; hi < 2; hi++) {
                    int row = row0 + hi * 8;
                    if (row < M) {
                        float2 v;
                        v.x = acc[mt][nt][hi * 2] + b0;
                        v.y = acc[mt][nt][hi * 2 + 1] + b1;
                        if (act) { v.x = fmaxf(v.x, 0.f); v.y = fmaxf(v.y, 0.f); }
                        *reinterpret_cast<float2*>(C + (size_t)row * ldc + col) = v;
                    }
                }
            }
        }
    }
}

// ---------------- split / convert kernels ----------------
__global__ void k_split(const float* __restrict__ in, __half* __restrict__ oh,
                        __half* __restrict__ ol, int R, int K, int Kp) {
    int idx = blockIdx.x * blockDim.x + threadIdx.x;
    if (idx >= R * Kp) return;
    int r = idx / Kp, c = idx - r * Kp;
    float v = (c < K) ? in[(size_t)r * K + c] : 0.f;
    splitw(v, oh[idx], ol[idx]);
}
__global__ void k_tohalf(const float* __restrict__ in, __half* __restrict__ oh,
                         int R, int K, int Kp) {
    int idx = blockIdx.x * blockDim.x + threadIdx.x;
    if (idx >= R * Kp) return;
    int r = idx / Kp, c = idx - r * Kp;
    float v = (c < K) ? in[(size_t)r * K + c] : 0.f;
    oh[idx] = __float2half_rn(v);
}
__global__ void k_splitfeats(const float* __restrict__ feats, __half* __restrict__ oh,
                             __half* __restrict__ ol) {
    int idx = blockIdx.x * blockDim.x + threadIdx.x;
    if (idx >= 2000 * 2048) return;
    int r = idx >> 11, c = idx & 2047;
    float v = (c < FIN) ? feats[r * FIN + c] : 0.f;
    splitw(v, oh[idx], ol[idx]);
}
__global__ void k_splitWc(const float* __restrict__ Wg, const float* __restrict__ Whh,
                          const float* __restrict__ bg, const float* __restrict__ bhh,
                          __half* __restrict__ oh, float* __restrict__ bc) {
    int idx = blockIdx.x * blockDim.x + threadIdx.x;
    if (idx >= 10000 * 2048) return;
    int r = idx >> 11, c = idx & 2047;
    float v = 0.f;
    if (c < 2000) v = (r < 4000) ? Wg[(size_t)r * 2000 + c] : Whh[(size_t)(r - 4000) * 2000 + c];
    oh[idx] = __float2half_rn(v);
    if (idx < 10000) bc[idx] = (idx < 4000) ? bg[idx] : bhh[idx - 4000];
}

// ---------------- CSR build ----------------
__global__ void k_zero_int(int* p, int n) {
    int i = blockIdx.x * blockDim.x + threadIdx.x;
    if (i < n) p[i] = 0;
}
__global__ void k_count(const int* __restrict__ dst, int* cnt) {
    int i = blockIdx.x * blockDim.x + threadIdx.x;
    if (i < EE) atomicAdd(&cnt[dst[i]], 1);
}
__global__ void k_scan(const int* __restrict__ cnt, int* __restrict__ off) {
    int tid = threadIdx.x;
    int a = (2 * tid < NN) ? cnt[2 * tid] : 0;
    int b = (2 * tid + 1 < NN) ? cnt[2 * tid + 1] : 0;
    int ts = a + b;
    int lane = tid & 31, wid = tid >> 5;
    int v = ts;
#pragma unroll
    for (int d = 1; d < 32; d <<= 1) {
        int u = __shfl_up_sync(0xffffffffu, v, d);
        if (lane >= d) v += u;
    }
    __shared__ int ws[32];
    if (lane == 31) ws[wid] = v;
    __syncthreads();
    if (wid == 0) {
        int w = ws[lane];
#pragma unroll
        for (int d = 1; d < 32; d <<= 1) {
            int u = __shfl_up_sync(0xffffffffu, w, d);
            if (lane >= d) w += u;
        }
        ws[lane] = w;
    }
    __syncthreads();
    int incl = v + (wid > 0 ? ws[wid - 1] : 0);
    int excl = incl - ts;
    if (2 * tid <= NN) off[2 * tid] = excl;
    if (2 * tid + 1 <= NN) off[2 * tid + 1] = excl + a;
}
__global__ void k_fill(const int* __restrict__ src, const int* __restrict__ dst,
                       const int* __restrict__ et, const int* __restrict__ off,
                       int* cnt, int* __restrict__ csr) {
    int i = blockIdx.x * blockDim.x + threadIdx.x;
    if (i < EE) {
        int d = dst[i];
        int p = off[d] + atomicAdd(&cnt[d], 1);
        csr[p] = src[i] * 2 + et[i];
    }
}
__global__ void k_boff(const int* __restrict__ batch, int* boff) {
    int i = blockIdx.x * blockDim.x + threadIdx.x;
    if (i >= NN) return;
    int b = batch[i];
    if (i == 0) {
        for (int x = 0; x <= b; x++) boff[x] = 0;
    } else {
        int pb = batch[i - 1];
        if (pb != b) for (int x = pb + 1; x <= b; x++) boff[x] = i;
    }
    if (i == NN - 1) {
        for (int x = b + 1; x <= BB; x++) boff[x] = NN;
    }
}

// ---------------- GGNN pieces (fused splits) ----------------
__global__ void k_hinit(const float* __restrict__ feats, float* __restrict__ h) {
    int i = blockIdx.x * blockDim.x + threadIdx.x;
    if (i >= NN * HH) return;
    int r = i / HH, c = i % HH;
    h[i] = (c < FIN) ? feats[r * FIN + c] : 0.f;
}
__global__ void k_agg(const float* __restrict__ tg, const int* __restrict__ off,
                      const int* __restrict__ csr, __half* __restrict__ ah,
                      __half* __restrict__ al) {
    int d = blockIdx.x;
    int j = blockIdx.y * 256 + threadIdx.x;
    size_t o = (size_t)d * 2048 + j;
    if (j >= 2000) { ah[o] = __half(0.f); al[o] = __half(0.f); return; }
    int s0 = off[d], s1 = off[d + 1];
    float acc = 0.f;
    for (int p = s0; p < s1; p++) {
        int v = csr[p];
        int sn = v >> 1, e = v & 1;
        acc += tg[(size_t)sn * 10000 + e * 2000 + j];
    }
    splitw(acc, ah[o], al[o]);
}
__global__ void k_cell(const float* __restrict__ gi, const float* __restrict__ tg,
                       float* __restrict__ h, __half* __restrict__ hh,
                       __half* __restrict__ hl) {
    int i = blockIdx.x * blockDim.x + threadIdx.x;
    if (i >= NN * HH) return;
    int r = i / HH, c = i % HH;
    size_t gI = (size_t)r * 6000 + c;
    size_t gH = (size_t)r * 10000 + 4000 + c;
    float rr = sigm(gi[gI] + tg[gH]);
    float zz = sigm(gi[gI + 2000] + tg[gH + 2000]);
    float nn = tanhf(gi[gI + 4000] + rr * tg[gH + 4000]);
    float hv = (1.f - zz) * nn + zz * h[i];
    h[i] = hv;
    size_t o = (size_t)r * 2048 + c;
    splitw(hv, hh[o], hl[o]);
}
__global__ void k_segmax(const float* __restrict__ h, const int* __restrict__ boff,
                         __half* __restrict__ ch, __half* __restrict__ cl) {
    int b = blockIdx.y;
    int j = blockIdx.x * 256 + threadIdx.x;
    if (j >= HH) return;
    int s = boff[b], e = boff[b + 1];
    float m = -INFINITY;
    for (int i = s; i < e; i++) m = fmaxf(m, h[(size_t)i * HH + j]);
    splitw(m, ch[b * 3200 + j], cl[b * 3200 + j]);
}

// ---------------- token branch ----------------
__global__ void k_embed(const float* __restrict__ ew, const int* __restrict__ tokens,
                        __half* __restrict__ xh, __half* __restrict__ xl) {
    int tb = blockIdx.x;
    int t = tb / BB, b = tb % BB;
    int tok = tokens[b * LL + t];
    size_t ro = (size_t)tb * 448;
    for (int j = threadIdx.x; j < 448; j += blockDim.x) {
        float v = (j < FIN) ? ew[(size_t)tok * FIN + j] : 0.f;
        splitw(v, xh[ro + j], xl[ro + j]);
    }
}
__global__ void k_zpad(__half* __restrict__ xh, __half* __restrict__ xl) {
    int idx = blockIdx.x * blockDim.x + threadIdx.x;
    if (idx >= 4096 * 48) return;
    int r = idx / 48, c = 400 + idx % 48;
    xh[(size_t)r * 448 + c] = __half(0.f);
    xl[(size_t)r * 448 + c] = __half(0.f);
}
// W [6][600][200] fp32 -> WTh [6][200][600] fp16
__global__ void k_transpose_whh(const float* __restrict__ W, __half* __restrict__ WT) {
    int i = blockIdx.x * blockDim.x + threadIdx.x;
    if (i >= 6 * 600 * 200) return;
    int ld = i / (600 * 200);
    int rem = i % (600 * 200);
    int j = rem / 200, k = rem % 200;
    WT[ld * 120000 + k * 600 + j] = __float2half_rn(W[i]);
}

// GRU scan v3: ONE batch per CTA (32 CTAs = 2 dirs x 16 batches).
// fp16 W (uint4 = 8 j's per load), 8 k-slabs of 25 fully unrolled,
// gi prefetched into registers one step ahead.
__global__ __launch_bounds__(256) void k_gruscan(
    const float* __restrict__ giAll,
    const __half* __restrict__ WTl,      // [2][200][600] fp16
    const float* __restrict__ bhhl,
    __half* __restrict__ yh, __half* __restrict__ yl,   // [L*B][448]
    __half* __restrict__ ch, __half* __restrict__ cl,
    int layer)
{
    int cid = blockIdx.x;     // 0..31
    int dir = cid & 1;
    int b   = cid >> 1;       // batch 0..15
    const __half* W = WTl + dir * 120000;
    const float* bhh = bhhl + dir * 600;

    __shared__ float sh_h[200];
    __shared__ float sh_gi[600];
    __shared__ float red[8][3][200];

    int tid = threadIdx.x;
    int ks = tid >> 5;        // 0..7, k-slab of 25
    int jg = tid & 31;        // active < 25, 8 j's each

    for (int i = tid; i < 200; i += 256) sh_h[i] = 0.f;

    // preload gi for step 0 into registers
    float rg[3];
    {
        int t0 = dir ? (LL - 1) : 0;
        const float* g0 = giAll + ((size_t)(t0 * BB + b)) * 1200 + dir * 600;
#pragma unroll
        for (int q = 0; q < 3; q++) {
            int i = tid + q * 256;
            rg[q] = (i < 600) ? g0[i] : 0.f;
        }
    }
    __syncthreads();

    for (int s = 0; s < LL; s++) {
        // commit staged gi to smem
#pragma unroll
        for (int q = 0; q < 3; q++) {
            int i = tid + q * 256;
            if (i < 600) sh_gi[i] = rg[q];
        }
        __syncthreads();

        // stage next step's gi (latency overlaps matvec)
        if (s + 1 < LL) {
            int tn = dir ? (LL - 2 - s) : (s + 1);
            const float* gn = giAll + ((size_t)(tn * BB + b)) * 1200 + dir * 600;
#pragma unroll
            for (int q = 0; q < 3; q++) {
                int i = tid + q * 256;
                rg[q] = (i < 600) ? gn[i] : 0.f;
            }
        }

        // matvec partials: thread (ks, jg<25) covers k in [ks*25,+25), j in [jg*8,+8)
        if (jg < 25) {
            float acc[3][8];
#pragma unroll
            for (int g = 0; g < 3; g++)
#pragma unroll
                for (int jj = 0; jj < 8; jj++) acc[g][jj] = 0.f;
            int kb = ks * 25;
#pragma unroll
            for (int kk = 0; kk < 25; kk++) {
                int k = kb + kk;
                float hv = sh_h[k];
                const __half* row = W + k * 600;
#pragma unroll
                for (int g = 0; g < 3; g++) {
                    uint4 u = *reinterpret_cast<const uint4*>(row + g * 200 + jg * 8);
                    float2 f0 = __half22float2(*reinterpret_cast<__half2*>(&u.x));
                    float2 f1 = __half22float2(*reinterpret_cast<__half2*>(&u.y));
                    float2 f2 = __half22float2(*reinterpret_cast<__half2*>(&u.z));
                    float2 f3 = __half22float2(*reinterpret_cast<__half2*>(&u.w));
                    acc[g][0] += f0.x * hv; acc[g][1] += f0.y * hv;
                    acc[g][2] += f1.x * hv; acc[g][3] += f1.y * hv;
                    acc[g][4] += f2.x * hv; acc[g][5] += f2.y * hv;
                    acc[g][6] += f3.x * hv; acc[g][7] += f3.y * hv;
                }
            }
#pragma unroll
            for (int g = 0; g < 3; g++)
#pragma unroll
                for (int jj = 0; jj < 8; jj++)
                    red[ks][g][jg * 8 + jj] = acc[g][jj];
        }
        __syncthreads();

        // cell update
        if (tid < 200) {
            int j = tid;
            int t = dir ? (LL - 1 - s) : s;
            float gr = 0.f, gz = 0.f, gn2 = 0.f;
#pragma unroll
            for (int ki = 0; ki < 8; ki++) {
                gr += red[ki][0][j];
                gz += red[ki][1][j];
                gn2 += red[ki][2][j];
            }
            gr += bhh[j]; gz += bhh[200 + j]; gn2 += bhh[400 + j];
            float rr = sigm(sh_gi[j] + gr);
            float zz = sigm(sh_gi[200 + j] + gz);
            float nn = tanhf(sh_gi[400 + j] + rr * gn2);
            float hnew = (1.f - zz) * nn + zz * sh_h[j];
            size_t yo = ((size_t)(t * BB + b)) * 448 + dir * 200 + j;
            __half hh_ = __float2half_rn(hnew);
            __half hl_ = __float2half_rn(hnew - __half2float(hh_));
            yh[yo] = hh_; yl[yo] = hl_;
            if (s == LL - 1) {
                size_t co = (size_t)b * 3200 + 2000 + (2 * layer + dir) * 200 + j;
                ch[co] = hh_; cl[co] = hl_;
            }
            sh_h[j] = hnew;
        }
        __syncthreads();
    }
}

// ---------------- final tiny head layer (N=2) ----------------
__global__ void k_head2(const float* __restrict__ f2, const float* __restrict__ W,
                        const float* __restrict__ b, float* __restrict__ out) {
    int t = threadIdx.x;
    if (t >= 32) return;
    int bb = t >> 1, n = t & 1;
    float acc = 0.f;
    for (int k = 0; k < 500; k++) acc += f2[bb * 500 + k] * W[n * 500 + k];
    out[bb * 2 + n] = fmaxf(acc + b[n], 0.f);
}

// ---------------- host side ----------------
#define SYMP(p, s) do { void* _q = nullptr; cudaGetSymbolAddress(&_q, s); p = (decltype(p))_q; } while (0)

static void tcg(cudaStream_t st, const __half* Ah, const __half* Al, int ldA,
                const __half* Bh, int ldB,
                const float* bias, float* C, int ldc, int M, int N, int K, int act) {
    dim3 g((N + 63) / 64, (M + 127) / 128);
    hgemm<<<g, 256, SMEM_DYN, st>>>(Ah, Al, ldA, Bh, ldB, bias, C, ldc, M, N, K, act);
}

extern "C" void kernel_launch(void* const* d_in, const int* in_sizes, int n_in,
                              void* d_out, int out_size) {
    const float* feats   = (const float*)d_in[0];
    const int*   tokens  = (const int*)d_in[1];
    const int*   src     = (const int*)d_in[2];
    const int*   dst     = (const int*)d_in[3];
    const int*   etype   = (const int*)d_in[4];
    const int*   batch   = (const int*)d_in[5];
    const float* embed_w = (const float*)d_in[6];
    const float* ggnn_W  = (const float*)d_in[7];
    const float* ggnn_b  = (const float*)d_in[8];
    const float* Wih     = (const float*)d_in[9];
    const float* Whh     = (const float*)d_in[10];
    const float* bih     = (const float*)d_in[11];
    const float* bhh     = (const float*)d_in[12];
    const float* gWih    = (const float*)d_in[13];
    const float* gWhh    = (const float*)d_in[14];
    const float* gbih    = (const float*)d_in[15];
    const float* gbhh    = (const float*)d_in[16];
    const float* l1W = (const float*)d_in[17]; const float* l1b = (const float*)d_in[18];
    const float* l11W = (const float*)d_in[19]; const float* l11b = (const float*)d_in[20];
    const float* l2W = (const float*)d_in[21]; const float* l2b = (const float*)d_in[22];
    float* out = (float*)d_out;

    static bool sinit = false;
    static cudaStream_t s1;
    static cudaEvent_t eF, eJ;
    if (!sinit) {
        cudaFuncSetAttribute(hgemm, cudaFuncAttributeMaxDynamicSharedMemorySize, SMEM_DYN);
        cudaStreamCreateWithFlags(&s1, cudaStreamNonBlocking);
        cudaEventCreateWithFlags(&eF, cudaEventDisableTiming);
        cudaEventCreateWithFlags(&eJ, cudaEventDisableTiming);
        sinit = true;
    }

    float *p_h, *p_tg, *p_gi, *p_gt, *p_f1, *p_f2, *p_bc;
    int *p_off, *p_cnt, *p_csr, *p_boff;
    __half *hh, *hl, *ah, *al, *Wch, *Wihh, *gWh, *p_WTh;
    __half *l1h, *l11h, *xh, *xl, *x2h, *x2l, *ch, *cl, *f1h, *f1l;
    SYMP(p_h, g_h);   SYMP(p_tg, g_tg); SYMP(p_gi, g_gi);
    SYMP(p_off, g_off); SYMP(p_cnt, g_cnt); SYMP(p_csr, g_csr); SYMP(p_boff, g_boff);
    SYMP(p_gt, g_gt); SYMP(p_f1, g_f1); SYMP(p_f2, g_f2); SYMP(p_bc, g_bc);
    SYMP(hh, g_hh); SYMP(hl, g_hl); SYMP(ah, g_ah); SYMP(al, g_al);
    SYMP(Wch, g_Wch); SYMP(Wihh, g_Wihh); SYMP(gWh, g_gWh); SYMP(p_WTh, g_WTh);
    SYMP(l1h, g_l1h); SYMP(l11h, g_l11h);
    SYMP(xh, g_xh); SYMP(xl, g_xl); SYMP(x2h, g_x2h); SYMP(x2l, g_x2l);
    SYMP(ch, g_ch); SYMP(cl, g_cl); SYMP(f1h, g_f1h); SYMP(f1l, g_f1l);

    // fork event (token branch depends only on inputs)
    cudaEventRecord(eF, 0);

    // ---- GGNN prep + first GEMMs ----
    k_splitfeats<<<(2000 * 2048 + 255) / 256, 256>>>(feats, hh, hl);
    k_splitWc<<<(10000 * 2048 + 255) / 256, 256>>>(ggnn_W, Whh, ggnn_b, bhh, Wch, p_bc);
    tcg(0, hh, hl, 2048, Wch, 2048, p_bc, p_tg, 10000, NN, 5000, 128, 0);
    tcg(0, hh, hl, 2048, Wch + (size_t)5000 * 2048, 2048,
        p_bc + 5000, p_tg + 5000, 10000, NN, 5000, 128, 0);
    k_hinit<<<(NN * HH + 255) / 256, 256>>>(feats, p_h);

    // CSR + batch offsets
    k_zero_int<<<(NN + 255) / 256, 256>>>(p_cnt, NN);
    k_count<<<(EE + 255) / 256, 256>>>(dst, p_cnt);
    k_scan<<<1, 1024>>>(p_cnt, p_off);
    k_zero_int<<<(NN + 255) / 256, 256>>>(p_cnt, NN);
    k_fill<<<(EE + 255) / 256, 256>>>(src, dst, etype, p_off, p_cnt, p_csr);
    k_boff<<<(NN + 255) / 256, 256>>>(batch, p_boff);

    // B-side weight conversions (hi only)
    k_tohalf<<<(6000 * 2048 + 255) / 256, 256>>>(Wih, Wihh, 6000, 2000, 2048);
    k_tohalf<<<(1000 * 3200 + 255) / 256, 256>>>(l1W, l1h, 1000, 3200, 3200);
    k_tohalf<<<(500 * 1024 + 255) / 256, 256>>>(l11W, l11h, 500, 1000, 1024);

    // ---- GGNN steps ----
    for (int step = 0; step < 3; step++) {
        if (step > 0)
            tcg(0, hh, hl, 2048, Wch, 2048, p_bc, p_tg, 10000, NN, 10000, 2048, 0);
        k_agg<<<dim3(NN, 8), 256>>>(p_tg, p_off, p_csr, ah, al);
        tcg(0, ah, al, 2048, Wihh, 2048, bih, p_gi, 6000, NN, 6000, 2048, 0);
        k_cell<<<(NN * HH + 255) / 256, 256>>>(p_gi, p_tg, p_h, hh, hl);
    }
    k_segmax<<<dim3(8, BB), 256>>>(p_h, p_boff, ch, cl);

    // ---- token branch on s1 (forked; joins before head) ----
    cudaStreamWaitEvent(s1, eF, 0);
    k_embed<<<LL * BB, 128, 0, s1>>>(embed_w, tokens, xh, xl);
    k_zpad<<<(4096 * 48 + 255) / 256, 256, 0, s1>>>(x2h, x2l);
    k_transpose_whh<<<(6 * 600 * 200 + 255) / 256, 256, 0, s1>>>(gWhh, p_WTh);
    k_tohalf<<<(3600 * 448 + 255) / 256, 256, 0, s1>>>(gWih, gWh, 3600, 400, 448);

    __half* inh = xh;  __half* inl = xl;
    __half* outh = x2h; __half* outl = x2l;
    for (int l = 0; l < 3; l++) {
        tcg(s1, inh, inl, 448, gWh + (size_t)l * 1200 * 448, 448,
            gbih + l * 1200, p_gt, 1200, LL * BB, 1200, 448, 0);
        k_gruscan<<<32, 256, 0, s1>>>(p_gt, p_WTh + l * 240000, gbhh + l * 1200,
                                      outh, outl, ch, cl, l);
        __half* t1 = inh; inh = outh; outh = t1;
        __half* t2 = inl; inl = outl; outl = t2;
    }
    cudaEventRecord(eJ, s1);
    cudaStreamWaitEvent(0, eJ, 0);

    // ---- head (needs both branches) ----
    tcg(0, ch, cl, 3200, l1h, 3200, l1b, p_f1, 1000, BB, 1000, 3200, 1);
    k_split<<<(16 * 1024 + 255) / 256, 256>>>(p_f1, f1h, f1l, BB, 1000, 1024);
    tcg(0, f1h, f1l, 1024, l11h, 1024, l11b, p_f2, 500, BB, 500, 1024, 1);
    k_head2<<<1, 32>>>(p_f2, l2W, l2b, out);

    (void)in_sizes; (void)n_in; (void)out_size;
}

// round 16
// speedup vs baseline: 2.9932x; 1.0458x over previous
#include <cuda_runtime.h>
#include <cuda_fp16.h>
#include <stdint.h>
#include <math.h>

#define NN 2000
#define EE 16000
#define BB 16
#define LL 256
#define HH 2000
#define FIN 100
#define GG 200

// ---------------- scratch (device globals; no cudaMalloc allowed) ----------------
__device__ float g_h[(size_t)NN * HH];
__device__ float g_tg[(size_t)NN * 10000];
__device__ float g_gi[(size_t)NN * 3 * HH];
__device__ int   g_off[NN + 1];
__device__ int   g_cnt[NN];
__device__ int   g_csr[EE];
__device__ int   g_boff[BB + 1];
__device__ float g_gt[(size_t)LL * BB * 1200];
__device__ float g_f1[BB * 1000];
__device__ float g_f2[BB * 500];
__device__ float g_bc[10000];

__device__ __half g_hh[(size_t)2000 * 2048], g_hl[(size_t)2000 * 2048];
__device__ __half g_ah[(size_t)2000 * 2048], g_al[(size_t)2000 * 2048];
__device__ __half g_Wch[(size_t)10000 * 2048];
__device__ __half g_Wihh[(size_t)6000 * 2048];
__device__ __half g_gWh[(size_t)3600 * 448];
__device__ __half g_l1h[(size_t)1000 * 3200];
__device__ __half g_l11h[(size_t)500 * 1024];
__device__ __half g_WTh[3 * 2 * 200 * 600];
__device__ __half g_xh[(size_t)4096 * 448], g_xl[(size_t)4096 * 448];
__device__ __half g_x2h[(size_t)4096 * 448], g_x2l[(size_t)4096 * 448];
__device__ __half g_ch[(size_t)16 * 3200], g_cl[(size_t)16 * 3200];
__device__ __half g_f1h[(size_t)16 * 1024], g_f1l[(size_t)16 * 1024];

// ---------------- small helpers ----------------
__device__ __forceinline__ float sigm(float x) { return 1.f / (1.f + expf(-x)); }
__device__ __forceinline__ void splitw(float v, __half& h, __half& l) {
    h = __float2half_rn(v);
    l = __float2half_rn(v - __half2float(h));
}
__device__ __forceinline__ uint32_t s2u(const void* p) {
    uint32_t a;
    asm("{ .reg .u64 t; cvta.to.shared.u64 t, %1; cvt.u32.u64 %0, t; }" : "=r"(a) : "l"(p));
    return a;
}
__device__ __forceinline__ void cpa16(uint32_t dst, const void* src, uint32_t sz) {
    asm volatile("cp.async.ca.shared.global [%0], [%1], 16, %2;" :: "r"(dst), "l"(src), "r"(sz));
}
__device__ __forceinline__ void ldm4(uint32_t* r, uint32_t addr) {
    asm volatile("ldmatrix.sync.aligned.m8n8.x4.shared.b16 {%0,%1,%2,%3}, [%4];"
                 : "=r"(r[0]), "=r"(r[1]), "=r"(r[2]), "=r"(r[3]) : "r"(addr));
}
__device__ __forceinline__ void hmma(float* c, const uint32_t* a, const uint32_t* b) {
    asm volatile("mma.sync.aligned.m16n8k16.row.col.f32.f16.f16.f32 "
                 "{%0,%1,%2,%3},{%4,%5,%6,%7},{%8,%9},{%0,%1,%2,%3};"
                 : "+f"(c[0]), "+f"(c[1]), "+f"(c[2]), "+f"(c[3])
                 : "r"(a[0]), "r"(a[1]), "r"(a[2]), "r"(a[3]), "r"(b[0]), "r"(b[1]));
}

#define RS 144
#define MATAB (128 * RS)
#define MATBB (64 * RS)

// ============ 2-term GEMM: C = act((Ah+Al) @ Bh^T + bias) ============
#define BUFB (2 * MATAB + MATBB)
#define SMEM_DYN (2 * BUFB)

__global__ __launch_bounds__(256, 2) void hgemm(
    const __half* __restrict__ Ah, const __half* __restrict__ Al, int ldA,
    const __half* __restrict__ Bh, int ldB,
    const float* __restrict__ bias, float* __restrict__ C, int ldc,
    int M, int N, int K, int act)
{
    extern __shared__ char smem[];
    const uint32_t sb = s2u(smem);
    const int tid = threadIdx.x;
    const int warp = tid >> 5, lane = tid & 31;
    const int wm = warp & 3, wn = warp >> 2;
    const int br = blockIdx.y * 128, bc = blockIdx.x * 64;
    const int nk = K >> 6;

    float acc[2][4][4];
#pragma unroll
    for (int mt = 0; mt < 2; mt++)
#pragma unroll
        for (int nt = 0; nt < 4; nt++)
#pragma unroll
            for (int r = 0; r < 4; r++) acc[mt][nt][r] = 0.f;

    auto issue = [&](int c) {
        uint32_t tb = sb + (uint32_t)(c & 1) * BUFB;
        int k0 = c << 6;
#pragma unroll
        for (int i = 0; i < 10; i++) {
            int g = (i << 8) + tid;
            if (g < 2048) {
                int which = g >> 10;
                int row = (g >> 3) & 127;
                int kb = g & 7;
                uint32_t dst = tb + which * MATAB + row * RS + kb * 16;
                int gr = br + row;
                const __half* base = which ? Al : Ah;
                uint32_t sz = (gr < M) ? 16u : 0u;
                cpa16(dst, base + (size_t)(gr < M ? gr : 0) * ldA + k0 + kb * 8, sz);
            } else {
                int g2 = g - 2048;
                int row = g2 >> 3;
                int kb = g2 & 7;
                uint32_t dst = tb + 2 * MATAB + row * RS + kb * 16;
                int gn = bc + row;
                uint32_t sz = (gn < N) ? 16u : 0u;
                cpa16(dst, Bh + (size_t)(gn < N ? gn : 0) * ldB + k0 + kb * 8, sz);
            }
        }
        asm volatile("cp.async.commit_group;");
    };

    const int arow = wm * 32 + (lane & 15);
    const int ak = (lane >> 4);
    const int brow = wn * 32 + (lane & 7) + ((lane >> 4) << 3);
    const int bk = ((lane >> 3) & 1);

    auto compute = [&](int c) {
        uint32_t tb = sb + (uint32_t)(c & 1) * BUFB;
        uint32_t aAh = tb, aAl = tb + MATAB, aBh = tb + 2 * MATAB;
#pragma unroll
        for (int k16 = 0; k16 < 4; k16++) {
            uint32_t ah[2][4], al[2][4];
#pragma unroll
            for (int mt = 0; mt < 2; mt++) {
                uint32_t off = (uint32_t)(arow + mt * 16) * RS + (2 * k16 + ak) * 16;
                ldm4(ah[mt], aAh + off);
                ldm4(al[mt], aAl + off);
            }
            uint32_t bh[4][2];
#pragma unroll
            for (int np = 0; np < 2; np++) {
                uint32_t off = (uint32_t)(brow + np * 16) * RS + (2 * k16 + bk) * 16;
                uint32_t t4[4];
                ldm4(t4, aBh + off);
                bh[np * 2][0] = t4[0]; bh[np * 2][1] = t4[1];
                bh[np * 2 + 1][0] = t4[2]; bh[np * 2 + 1][1] = t4[3];
            }
#pragma unroll
            for (int mt = 0; mt < 2; mt++)
#pragma unroll
                for (int nt = 0; nt < 4; nt++) {
                    hmma(acc[mt][nt], ah[mt], bh[nt]);
                    hmma(acc[mt][nt], al[mt], bh[nt]);
                }
        }
    };

    issue(0);
    for (int c = 0; c < nk; c++) {
        if (c + 1 < nk) {
            issue(c + 1);
            asm volatile("cp.async.wait_group 1;" ::: "memory");
        } else {
            asm volatile("cp.async.wait_group 0;" ::: "memory");
        }
        __syncthreads();
        compute(c);
        __syncthreads();
    }

#pragma unroll
    for (int mt = 0; mt < 2; mt++) {
        int row0 = br + wm * 32 + mt * 16 + (lane >> 2);
#pragma unroll
        for (int nt = 0; nt < 4; nt++) {
            int col = bc + wn * 32 + nt * 8 + ((lane & 3) << 1);
            if (col < N) {
                float b0 = bias ? bias[col] : 0.f;
                float b1 = bias ? bias[col + 1] : 0.f;
#pragma unroll
                for (int hi = 0; hi < 2; hi++) {
                    int row = row0 + hi * 8;
                    if (row < M) {
                        float2 v;
                        v.x = acc[mt][nt][hi * 2] + b0;
                        v.y = acc[mt][nt][hi * 2 + 1] + b1;
                        if (act) { v.x = fmaxf(v.x, 0.f); v.y = fmaxf(v.y, 0.f); }
                        *reinterpret_cast<float2*>(C + (size_t)row * ldc + col) = v;
                    }
                }
            }
        }
    }
}

// ============ 1-term GEMM: C = act(Ah @ Bh^T + bias)  (pure fp16 operands) ====
#define BUFB1 (MATAB + MATBB)
#define SMEM_DYN1 (2 * BUFB1)

__global__ __launch_bounds__(256, 2) void hgemm1(
    const __half* __restrict__ Ah, int ldA,
    const __half* __restrict__ Bh, int ldB,
    const float* __restrict__ bias, float* __restrict__ C, int ldc,
    int M, int N, int K, int act)
{
    extern __shared__ char smem[];
    const uint32_t sb = s2u(smem);
    const int tid = threadIdx.x;
    const int warp = tid >> 5, lane = tid & 31;
    const int wm = warp & 3, wn = warp >> 2;
    const int br = blockIdx.y * 128, bc = blockIdx.x * 64;
    const int nk = K >> 6;

    float acc[2][4][4];
#pragma unroll
    for (int mt = 0; mt < 2; mt++)
#pragma unroll
        for (int nt = 0; nt < 4; nt++)
#pragma unroll
            for (int r = 0; r < 4; r++) acc[mt][nt][r] = 0.f;

    auto issue = [&](int c) {
        uint32_t tb = sb + (uint32_t)(c & 1) * BUFB1;
        int k0 = c << 6;
#pragma unroll
        for (int i = 0; i < 6; i++) {
            int g = (i << 8) + tid;           // 0..1535
            if (g < 1024) {
                int row = g >> 3;
                int kb = g & 7;
                uint32_t dst = tb + row * RS + kb * 16;
                int gr = br + row;
                uint32_t sz = (gr < M) ? 16u : 0u;
                cpa16(dst, Ah + (size_t)(gr < M ? gr : 0) * ldA + k0 + kb * 8, sz);
            } else {
                int g2 = g - 1024;            // 0..511
                int row = g2 >> 3;
                int kb = g2 & 7;
                uint32_t dst = tb + MATAB + row * RS + kb * 16;
                int gn = bc + row;
                uint32_t sz = (gn < N) ? 16u : 0u;
                cpa16(dst, Bh + (size_t)(gn < N ? gn : 0) * ldB + k0 + kb * 8, sz);
            }
        }
        asm volatile("cp.async.commit_group;");
    };

    const int arow = wm * 32 + (lane & 15);
    const int ak = (lane >> 4);
    const int brow = wn * 32 + (lane & 7) + ((lane >> 4) << 3);
    const int bk = ((lane >> 3) & 1);

    auto compute = [&](int c) {
        uint32_t tb = sb + (uint32_t)(c & 1) * BUFB1;
        uint32_t aAh = tb, aBh = tb + MATAB;
#pragma unroll
        for (int k16 = 0; k16 < 4; k16++) {
            uint32_t ah[2][4];
#pragma unroll
            for (int mt = 0; mt < 2; mt++) {
                uint32_t off = (uint32_t)(arow + mt * 16) * RS + (2 * k16 + ak) * 16;
                ldm4(ah[mt], aAh + off);
            }
            uint32_t bh[4][2];
#pragma unroll
            for (int np = 0; np < 2; np++) {
                uint32_t off = (uint32_t)(brow + np * 16) * RS + (2 * k16 + bk) * 16;
                uint32_t t4[4];
                ldm4(t4, aBh + off);
                bh[np * 2][0] = t4[0]; bh[np * 2][1] = t4[1];
                bh[np * 2 + 1][0] = t4[2]; bh[np * 2 + 1][1] = t4[3];
            }
#pragma unroll
            for (int mt = 0; mt < 2; mt++)
#pragma unroll
                for (int nt = 0; nt < 4; nt++)
                    hmma(acc[mt][nt], ah[mt], bh[nt]);
        }
    };

    issue(0);
    for (int c = 0; c < nk; c++) {
        if (c + 1 < nk) {
            issue(c + 1);
            asm volatile("cp.async.wait_group 1;" ::: "memory");
        } else {
            asm volatile("cp.async.wait_group 0;" ::: "memory");
        }
        __syncthreads();
        compute(c);
        __syncthreads();
    }

#pragma unroll
    for (int mt = 0; mt < 2; mt++) {
        int row0 = br + wm * 32 + mt * 16 + (lane >> 2);
#pragma unroll
        for (int nt = 0; nt < 4; nt++) {
            int col = bc + wn * 32 + nt * 8 + ((lane & 3) << 1);
            if (col < N) {
                float b0 = bias ? bias[col] : 0.f;
                float b1 = bias ? bias[col + 1] : 0.f;
#pragma unroll
                for (int hi = 0; hi < 2; hi++) {
                    int row = row0 + hi * 8;
                    if (row < M) {
                        float2 v;
                        v.x = acc[mt][nt][hi * 2] + b0;
                        v.y = acc[mt][nt][hi * 2 + 1] + b1;
                        if (act) { v.x = fmaxf(v.x, 0.f); v.y = fmaxf(v.y, 0.f); }
                        *reinterpret_cast<float2*>(C + (size_t)row * ldc + col) = v;
                    }
                }
            }
        }
    }
}

// ---------------- split / convert kernels ----------------
__global__ void k_split(const float* __restrict__ in, __half* __restrict__ oh,
                        __half* __restrict__ ol, int R, int K, int Kp) {
    int idx = blockIdx.x * blockDim.x + threadIdx.x;
    if (idx >= R * Kp) return;
    int r = idx / Kp, c = idx - r * Kp;
    float v = (c < K) ? in[(size_t)r * K + c] : 0.f;
    splitw(v, oh[idx], ol[idx]);
}
__global__ void k_tohalf(const float* __restrict__ in, __half* __restrict__ oh,
                         int R, int K, int Kp) {
    int idx = blockIdx.x * blockDim.x + threadIdx.x;
    if (idx >= R * Kp) return;
    int r = idx / Kp, c = idx - r * Kp;
    float v = (c < K) ? in[(size_t)r * K + c] : 0.f;
    oh[idx] = __float2half_rn(v);
}
__global__ void k_splitfeats(const float* __restrict__ feats, __half* __restrict__ oh,
                             __half* __restrict__ ol) {
    int idx = blockIdx.x * blockDim.x + threadIdx.x;
    if (idx >= 2000 * 2048) return;
    int r = idx >> 11, c = idx & 2047;
    float v = (c < FIN) ? feats[r * FIN + c] : 0.f;
    splitw(v, oh[idx], ol[idx]);
}
__global__ void k_splitWc(const float* __restrict__ Wg, const float* __restrict__ Whh,
                          const float* __restrict__ bg, const float* __restrict__ bhh,
                          __half* __restrict__ oh, float* __restrict__ bc) {
    int idx = blockIdx.x * blockDim.x + threadIdx.x;
    if (idx >= 10000 * 2048) return;
    int r = idx >> 11, c = idx & 2047;
    float v = 0.f;
    if (c < 2000) v = (r < 4000) ? Wg[(size_t)r * 2000 + c] : Whh[(size_t)(r - 4000) * 2000 + c];
    oh[idx] = __float2half_rn(v);
    if (idx < 10000) bc[idx] = (idx < 4000) ? bg[idx] : bhh[idx - 4000];
}

// ---------------- CSR build ----------------
__global__ void k_zero_int(int* p, int n) {
    int i = blockIdx.x * blockDim.x + threadIdx.x;
    if (i < n) p[i] = 0;
}
__global__ void k_count(const int* __restrict__ dst, int* cnt) {
    int i = blockIdx.x * blockDim.x + threadIdx.x;
    if (i < EE) atomicAdd(&cnt[dst[i]], 1);
}
__global__ void k_scan(const int* __restrict__ cnt, int* __restrict__ off) {
    int tid = threadIdx.x;
    int a = (2 * tid < NN) ? cnt[2 * tid] : 0;
    int b = (2 * tid + 1 < NN) ? cnt[2 * tid + 1] : 0;
    int ts = a + b;
    int lane = tid & 31, wid = tid >> 5;
    int v = ts;
#pragma unroll
    for (int d = 1; d < 32; d <<= 1) {
        int u = __shfl_up_sync(0xffffffffu, v, d);
        if (lane >= d) v += u;
    }
    __shared__ int ws[32];
    if (lane == 31) ws[wid] = v;
    __syncthreads();
    if (wid == 0) {
        int w = ws[lane];
#pragma unroll
        for (int d = 1; d < 32; d <<= 1) {
            int u = __shfl_up_sync(0xffffffffu, w, d);
            if (lane >= d) w += u;
        }
        ws[lane] = w;
    }
    __syncthreads();
    int incl = v + (wid > 0 ? ws[wid - 1] : 0);
    int excl = incl - ts;
    if (2 * tid <= NN) off[2 * tid] = excl;
    if (2 * tid + 1 <= NN) off[2 * tid + 1] = excl + a;
}
__global__ void k_fill(const int* __restrict__ src, const int* __restrict__ dst,
                       const int* __restrict__ et, const int* __restrict__ off,
                       int* cnt, int* __restrict__ csr) {
    int i = blockIdx.x * blockDim.x + threadIdx.x;
    if (i < EE) {
        int d = dst[i];
        int p = off[d] + atomicAdd(&cnt[d], 1);
        csr[p] = src[i] * 2 + et[i];
    }
}
__global__ void k_boff(const int* __restrict__ batch, int* boff) {
    int i = blockIdx.x * blockDim.x + threadIdx.x;
    if (i >= NN) return;
    int b = batch[i];
    if (i == 0) {
        for (int x = 0; x <= b; x++) boff[x] = 0;
    } else {
        int pb = batch[i - 1];
        if (pb != b) for (int x = pb + 1; x <= b; x++) boff[x] = i;
    }
    if (i == NN - 1) {
        for (int x = b + 1; x <= BB; x++) boff[x] = NN;
    }
}

// ---------------- GGNN pieces (fused splits) ----------------
__global__ void k_hinit(const float* __restrict__ feats, float* __restrict__ h) {
    int i = blockIdx.x * blockDim.x + threadIdx.x;
    if (i >= NN * HH) return;
    int r = i / HH, c = i % HH;
    h[i] = (c < FIN) ? feats[r * FIN + c] : 0.f;
}
__global__ void k_agg(const float* __restrict__ tg, const int* __restrict__ off,
                      const int* __restrict__ csr, __half* __restrict__ ah,
                      __half* __restrict__ al) {
    int d = blockIdx.x;
    int j = blockIdx.y * 256 + threadIdx.x;
    size_t o = (size_t)d * 2048 + j;
    if (j >= 2000) { ah[o] = __half(0.f); al[o] = __half(0.f); return; }
    int s0 = off[d], s1 = off[d + 1];
    float acc = 0.f;
    for (int p = s0; p < s1; p++) {
        int v = csr[p];
        int sn = v >> 1, e = v & 1;
        acc += tg[(size_t)sn * 10000 + e * 2000 + j];
    }
    splitw(acc, ah[o], al[o]);
}
__global__ void k_cell(const float* __restrict__ gi, const float* __restrict__ tg,
                       float* __restrict__ h, __half* __restrict__ hh,
                       __half* __restrict__ hl) {
    int i = blockIdx.x * blockDim.x + threadIdx.x;
    if (i >= NN * HH) return;
    int r = i / HH, c = i % HH;
    size_t gI = (size_t)r * 6000 + c;
    size_t gH = (size_t)r * 10000 + 4000 + c;
    float rr = sigm(gi[gI] + tg[gH]);
    float zz = sigm(gi[gI + 2000] + tg[gH + 2000]);
    float nn = tanhf(gi[gI + 4000] + rr * tg[gH + 4000]);
    float hv = (1.f - zz) * nn + zz * h[i];
    h[i] = hv;
    size_t o = (size_t)r * 2048 + c;
    splitw(hv, hh[o], hl[o]);
}
__global__ void k_segmax(const float* __restrict__ h, const int* __restrict__ boff,
                         __half* __restrict__ ch, __half* __restrict__ cl) {
    int b = blockIdx.y;
    int j = blockIdx.x * 256 + threadIdx.x;
    if (j >= HH) return;
    int s = boff[b], e = boff[b + 1];
    float m = -INFINITY;
    for (int i = s; i < e; i++) m = fmaxf(m, h[(size_t)i * HH + j]);
    splitw(m, ch[b * 3200 + j], cl[b * 3200 + j]);
}

// ---------------- token branch ----------------
__global__ void k_embed(const float* __restrict__ ew, const int* __restrict__ tokens,
                        __half* __restrict__ xh, __half* __restrict__ xl) {
    int tb = blockIdx.x;
    int t = tb / BB, b = tb % BB;
    int tok = tokens[b * LL + t];
    size_t ro = (size_t)tb * 448;
    for (int j = threadIdx.x; j < 448; j += blockDim.x) {
        float v = (j < FIN) ? ew[(size_t)tok * FIN + j] : 0.f;
        splitw(v, xh[ro + j], xl[ro + j]);
    }
}
__global__ void k_zpad(__half* __restrict__ xh, __half* __restrict__ xl) {
    int idx = blockIdx.x * blockDim.x + threadIdx.x;
    if (idx >= 4096 * 48) return;
    int r = idx / 48, c = 400 + idx % 48;
    xh[(size_t)r * 448 + c] = __half(0.f);
    xl[(size_t)r * 448 + c] = __half(0.f);
}
__global__ void k_transpose_whh(const float* __restrict__ W, __half* __restrict__ WT) {
    int i = blockIdx.x * blockDim.x + threadIdx.x;
    if (i >= 6 * 600 * 200) return;
    int ld = i / (600 * 200);
    int rem = i % (600 * 200);
    int j = rem / 200, k = rem % 200;
    WT[ld * 120000 + k * 600 + j] = __float2half_rn(W[i]);
}

// GRU scan v3 (unchanged from round 15)
__global__ __launch_bounds__(256) void k_gruscan(
    const float* __restrict__ giAll,
    const __half* __restrict__ WTl,
    const float* __restrict__ bhhl,
    __half* __restrict__ yh, __half* __restrict__ yl,
    __half* __restrict__ ch, __half* __restrict__ cl,
    int layer)
{
    int cid = blockIdx.x;
    int dir = cid & 1;
    int b   = cid >> 1;
    const __half* W = WTl + dir * 120000;
    const float* bhh = bhhl + dir * 600;

    __shared__ float sh_h[200];
    __shared__ float sh_gi[600];
    __shared__ float red[8][3][200];

    int tid = threadIdx.x;
    int ks = tid >> 5;
    int jg = tid & 31;

    for (int i = tid; i < 200; i += 256) sh_h[i] = 0.f;

    float rg[3];
    {
        int t0 = dir ? (LL - 1) : 0;
        const float* g0 = giAll + ((size_t)(t0 * BB + b)) * 1200 + dir * 600;
#pragma unroll
        for (int q = 0; q < 3; q++) {
            int i = tid + q * 256;
            rg[q] = (i < 600) ? g0[i] : 0.f;
        }
    }
    __syncthreads();

    for (int s = 0; s < LL; s++) {
#pragma unroll
        for (int q = 0; q < 3; q++) {
            int i = tid + q * 256;
            if (i < 600) sh_gi[i] = rg[q];
        }
        __syncthreads();

        if (s + 1 < LL) {
            int tn = dir ? (LL - 2 - s) : (s + 1);
            const float* gn = giAll + ((size_t)(tn * BB + b)) * 1200 + dir * 600;
#pragma unroll
            for (int q = 0; q < 3; q++) {
                int i = tid + q * 256;
                rg[q] = (i < 600) ? gn[i] : 0.f;
            }
        }

        if (jg < 25) {
            float acc[3][8];
#pragma unroll
            for (int g = 0; g < 3; g++)
#pragma unroll
                for (int jj = 0; jj < 8; jj++) acc[g][jj] = 0.f;
            int kb = ks * 25;
#pragma unroll
            for (int kk = 0; kk < 25; kk++) {
                int k = kb + kk;
                float hv = sh_h[k];
                const __half* row = W + k * 600;
#pragma unroll
                for (int g = 0; g < 3; g++) {
                    uint4 u = *reinterpret_cast<const uint4*>(row + g * 200 + jg * 8);
                    float2 f0 = __half22float2(*reinterpret_cast<__half2*>(&u.x));
                    float2 f1 = __half22float2(*reinterpret_cast<__half2*>(&u.y));
                    float2 f2 = __half22float2(*reinterpret_cast<__half2*>(&u.z));
                    float2 f3 = __half22float2(*reinterpret_cast<__half2*>(&u.w));
                    acc[g][0] += f0.x * hv; acc[g][1] += f0.y * hv;
                    acc[g][2] += f1.x * hv; acc[g][3] += f1.y * hv;
                    acc[g][4] += f2.x * hv; acc[g][5] += f2.y * hv;
                    acc[g][6] += f3.x * hv; acc[g][7] += f3.y * hv;
                }
            }
#pragma unroll
            for (int g = 0; g < 3; g++)
#pragma unroll
                for (int jj = 0; jj < 8; jj++)
                    red[ks][g][jg * 8 + jj] = acc[g][jj];
        }
        __syncthreads();

        if (tid < 200) {
            int j = tid;
            int t = dir ? (LL - 1 - s) : s;
            float gr = 0.f, gz = 0.f, gn2 = 0.f;
#pragma unroll
            for (int ki = 0; ki < 8; ki++) {
                gr += red[ki][0][j];
                gz += red[ki][1][j];
                gn2 += red[ki][2][j];
            }
            gr += bhh[j]; gz += bhh[200 + j]; gn2 += bhh[400 + j];
            float rr = sigm(sh_gi[j] + gr);
            float zz = sigm(sh_gi[200 + j] + gz);
            float nn = tanhf(sh_gi[400 + j] + rr * gn2);
            float hnew = (1.f - zz) * nn + zz * sh_h[j];
            size_t yo = ((size_t)(t * BB + b)) * 448 + dir * 200 + j;
            __half hh_ = __float2half_rn(hnew);
            __half hl_ = __float2half_rn(hnew - __half2float(hh_));
            yh[yo] = hh_; yl[yo] = hl_;
            if (s == LL - 1) {
                size_t co = (size_t)b * 3200 + 2000 + (2 * layer + dir) * 200 + j;
                ch[co] = hh_; cl[co] = hl_;
            }
            sh_h[j] = hnew;
        }
        __syncthreads();
    }
}

// ---------------- final tiny head layer (N=2) ----------------
__global__ void k_head2(const float* __restrict__ f2, const float* __restrict__ W,
                        const float* __restrict__ b, float* __restrict__ out) {
    int t = threadIdx.x;
    if (t >= 32) return;
    int bb = t >> 1, n = t & 1;
    float acc = 0.f;
    for (int k = 0; k < 500; k++) acc += f2[bb * 500 + k] * W[n * 500 + k];
    out[bb * 2 + n] = fmaxf(acc + b[n], 0.f);
}

// ---------------- host side ----------------
#define SYMP(p, s) do { void* _q = nullptr; cudaGetSymbolAddress(&_q, s); p = (decltype(p))_q; } while (0)

static void tcg(cudaStream_t st, const __half* Ah, const __half* Al, int ldA,
                const __half* Bh, int ldB,
                const float* bias, float* C, int ldc, int M, int N, int K, int act) {
    dim3 g((N + 63) / 64, (M + 127) / 128);
    hgemm<<<g, 256, SMEM_DYN, st>>>(Ah, Al, ldA, Bh, ldB, bias, C, ldc, M, N, K, act);
}
static void tcg1(cudaStream_t st, const __half* Ah, int ldA,
                 const __half* Bh, int ldB,
                 const float* bias, float* C, int ldc, int M, int N, int K, int act) {
    dim3 g((N + 63) / 64, (M + 127) / 128);
    hgemm1<<<g, 256, SMEM_DYN1, st>>>(Ah, ldA, Bh, ldB, bias, C, ldc, M, N, K, act);
}

extern "C" void kernel_launch(void* const* d_in, const int* in_sizes, int n_in,
                              void* d_out, int out_size) {
    const float* feats   = (const float*)d_in[0];
    const int*   tokens  = (const int*)d_in[1];
    const int*   src     = (const int*)d_in[2];
    const int*   dst     = (const int*)d_in[3];
    const int*   etype   = (const int*)d_in[4];
    const int*   batch   = (const int*)d_in[5];
    const float* embed_w = (const float*)d_in[6];
    const float* ggnn_W  = (const float*)d_in[7];
    const float* ggnn_b  = (const float*)d_in[8];
    const float* Wih     = (const float*)d_in[9];
    const float* Whh     = (const float*)d_in[10];
    const float* bih     = (const float*)d_in[11];
    const float* bhh     = (const float*)d_in[12];
    const float* gWih    = (const float*)d_in[13];
    const float* gWhh    = (const float*)d_in[14];
    const float* gbih    = (const float*)d_in[15];
    const float* gbhh    = (const float*)d_in[16];
    const float* l1W = (const float*)d_in[17]; const float* l1b = (const float*)d_in[18];
    const float* l11W = (const float*)d_in[19]; const float* l11b = (const float*)d_in[20];
    const float* l2W = (const float*)d_in[21]; const float* l2b = (const float*)d_in[22];
    float* out = (float*)d_out;

    static bool sinit = false;
    static cudaStream_t s1;
    static cudaEvent_t eF, eJ;
    if (!sinit) {
        cudaFuncSetAttribute(hgemm, cudaFuncAttributeMaxDynamicSharedMemorySize, SMEM_DYN);
        cudaFuncSetAttribute(hgemm1, cudaFuncAttributeMaxDynamicSharedMemorySize, SMEM_DYN1);
        cudaStreamCreateWithFlags(&s1, cudaStreamNonBlocking);
        cudaEventCreateWithFlags(&eF, cudaEventDisableTiming);
        cudaEventCreateWithFlags(&eJ, cudaEventDisableTiming);
        sinit = true;
    }

    float *p_h, *p_tg, *p_gi, *p_gt, *p_f1, *p_f2, *p_bc;
    int *p_off, *p_cnt, *p_csr, *p_boff;
    __half *hh, *hl, *ah, *al, *Wch, *Wihh, *gWh, *p_WTh;
    __half *l1h, *l11h, *xh, *xl, *x2h, *x2l, *ch, *cl, *f1h, *f1l;
    SYMP(p_h, g_h);   SYMP(p_tg, g_tg); SYMP(p_gi, g_gi);
    SYMP(p_off, g_off); SYMP(p_cnt, g_cnt); SYMP(p_csr, g_csr); SYMP(p_boff, g_boff);
    SYMP(p_gt, g_gt); SYMP(p_f1, g_f1); SYMP(p_f2, g_f2); SYMP(p_bc, g_bc);
    SYMP(hh, g_hh); SYMP(hl, g_hl); SYMP(ah, g_ah); SYMP(al, g_al);
    SYMP(Wch, g_Wch); SYMP(Wihh, g_Wihh); SYMP(gWh, g_gWh); SYMP(p_WTh, g_WTh);
    SYMP(l1h, g_l1h); SYMP(l11h, g_l11h);
    SYMP(xh, g_xh); SYMP(xl, g_xl); SYMP(x2h, g_x2h); SYMP(x2l, g_x2l);
    SYMP(ch, g_ch); SYMP(cl, g_cl); SYMP(f1h, g_f1h); SYMP(f1l, g_f1l);

    cudaEventRecord(eF, 0);

    // ---- GGNN prep + first GEMMs (1-term fp16) ----
    k_splitfeats<<<(2000 * 2048 + 255) / 256, 256>>>(feats, hh, hl);
    k_splitWc<<<(10000 * 2048 + 255) / 256, 256>>>(ggnn_W, Whh, ggnn_b, bhh, Wch, p_bc);
    tcg1(0, hh, 2048, Wch, 2048, p_bc, p_tg, 10000, NN, 5000, 128, 0);
    tcg1(0, hh, 2048, Wch + (size_t)5000 * 2048, 2048,
         p_bc + 5000, p_tg + 5000, 10000, NN, 5000, 128, 0);
    k_hinit<<<(NN * HH + 255) / 256, 256>>>(feats, p_h);

    // CSR + batch offsets
    k_zero_int<<<(NN + 255) / 256, 256>>>(p_cnt, NN);
    k_count<<<(EE + 255) / 256, 256>>>(dst, p_cnt);
    k_scan<<<1, 1024>>>(p_cnt, p_off);
    k_zero_int<<<(NN + 255) / 256, 256>>>(p_cnt, NN);
    k_fill<<<(EE + 255) / 256, 256>>>(src, dst, etype, p_off, p_cnt, p_csr);
    k_boff<<<(NN + 255) / 256, 256>>>(batch, p_boff);

    // B-side weight conversions
    k_tohalf<<<(6000 * 2048 + 255) / 256, 256>>>(Wih, Wihh, 6000, 2000, 2048);
    k_tohalf<<<(1000 * 3200 + 255) / 256, 256>>>(l1W, l1h, 1000, 3200, 3200);
    k_tohalf<<<(500 * 1024 + 255) / 256, 256>>>(l11W, l11h, 500, 1000, 1024);

    // ---- GGNN steps (1-term fp16 GEMMs) ----
    for (int step = 0; step < 3; step++) {
        if (step > 0)
            tcg1(0, hh, 2048, Wch, 2048, p_bc, p_tg, 10000, NN, 10000, 2048, 0);
        k_agg<<<dim3(NN, 8), 256>>>(p_tg, p_off, p_csr, ah, al);
        tcg1(0, ah, 2048, Wihh, 2048, bih, p_gi, 6000, NN, 6000, 2048, 0);
        k_cell<<<(NN * HH + 255) / 256, 256>>>(p_gi, p_tg, p_h, hh, hl);
    }
    k_segmax<<<dim3(8, BB), 256>>>(p_h, p_boff, ch, cl);

    // ---- token branch on s1 (2-term, unchanged) ----
    cudaStreamWaitEvent(s1, eF, 0);
    k_embed<<<LL * BB, 128, 0, s1>>>(embed_w, tokens, xh, xl);
    k_zpad<<<(4096 * 48 + 255) / 256, 256, 0, s1>>>(x2h, x2l);
    k_transpose_whh<<<(6 * 600 * 200 + 255) / 256, 256, 0, s1>>>(gWhh, p_WTh);
    k_tohalf<<<(3600 * 448 + 255) / 256, 256, 0, s1>>>(gWih, gWh, 3600, 400, 448);

    __half* inh = xh;  __half* inl = xl;
    __half* outh = x2h; __half* outl = x2l;
    for (int l = 0; l < 3; l++) {
        tcg(s1, inh, inl, 448, gWh + (size_t)l * 1200 * 448, 448,
            gbih + l * 1200, p_gt, 1200, LL * BB, 1200, 448, 0);
        k_gruscan<<<32, 256, 0, s1>>>(p_gt, p_WTh + l * 240000, gbhh + l * 1200,
                                      outh, outl, ch, cl, l);
        __half* t1 = inh; inh = outh; outh = t1;
        __half* t2 = inl; inl = outl; outl = t2;
    }
    cudaEventRecord(eJ, s1);
    cudaStreamWaitEvent(0, eJ, 0);

    // ---- head (2-term, unchanged) ----
    tcg(0, ch, cl, 3200, l1h, 3200, l1b, p_f1, 1000, BB, 1000, 3200, 1);
    k_split<<<(16 * 1024 + 255) / 256, 256>>>(p_f1, f1h, f1l, BB, 1000, 1024);
    tcg(0, f1h, f1l, 1024, l11h, 1024, l11b, p_f2, 500, BB, 500, 1024, 1);
    k_head2<<<1, 32>>>(p_f2, l2W, l2b, out);

    (void)in_sizes; (void)n_in; (void)out_size;
}